// round 2
// baseline (speedup 1.0000x reference)
#include <cuda_runtime.h>
#include <math.h>
#include <stdint.h>

#define BC 8
#define NC 4096
#define CC 768
#define HC 12
#define DC 64
#define MC 64
#define BHC (BC*HC)

// ---------------- scratch (device globals; no allocation) ----------------
__device__ float g_Q[(size_t)BHC*NC*DC];     // [B,H,N,D], pre-scaled by 1/sqrt(D)
__device__ float g_K[(size_t)BHC*NC*DC];
__device__ float g_V[(size_t)BHC*NC*DC];
__device__ float g_Kl[(size_t)BHC*MC*DC];    // landmarks
__device__ float g_Ql[(size_t)BHC*MC*DC];
__device__ float g_inv[(size_t)BHC*MC*MC];   // pinv(kernel2)
__device__ float g_k3V[(size_t)BHC*MC*DC];   // kernel3 @ V
__device__ float g_SV[(size_t)BC*NC*CC];     // [B,N,C]

// ---------------- SGEMM 128x128x16, C = A * B^T (B row-major [n,k]) ------
// EPI==0: qkv (out/bias unused, scatter into g_Q/g_K/g_V)
// EPI==1: proj (A ignored, reads g_SV; adds bias + permuted V)
template<int EPI>
__global__ void __launch_bounds__(256, 2) sgemm_kernel(
    const float* __restrict__ A, const float* __restrict__ Bm,
    float* __restrict__ out, const float* __restrict__ bias)
{
    __shared__ float As[16][132];
    __shared__ float Bs[16][132];
    const float* Abase = (EPI == 1) ? (const float*)g_SV : A;
    int tid = threadIdx.x;
    int n0 = blockIdx.x * 128;
    int m0 = blockIdx.y * 128;
    int tx = tid & 15, ty = tid >> 4;
    int lrow = tid >> 2;
    int lcol = (tid & 3) << 2;

    float acc[8][8];
#pragma unroll
    for (int i = 0; i < 8; i++)
#pragma unroll
        for (int j = 0; j < 8; j++) acc[i][j] = 0.f;

    const float* Ap = Abase + (size_t)(m0 + lrow) * 768 + lcol;
    const float* Bp = Bm + (size_t)(n0 + lrow) * 768 + lcol;

    for (int k0 = 0; k0 < 768; k0 += 16) {
#pragma unroll
        for (int it = 0; it < 2; it++) {
            float4 va = *(const float4*)(Ap + (size_t)it * 64 * 768 + k0);
            As[lcol + 0][lrow + it * 64] = va.x;
            As[lcol + 1][lrow + it * 64] = va.y;
            As[lcol + 2][lrow + it * 64] = va.z;
            As[lcol + 3][lrow + it * 64] = va.w;
            float4 vb = *(const float4*)(Bp + (size_t)it * 64 * 768 + k0);
            Bs[lcol + 0][lrow + it * 64] = vb.x;
            Bs[lcol + 1][lrow + it * 64] = vb.y;
            Bs[lcol + 2][lrow + it * 64] = vb.z;
            Bs[lcol + 3][lrow + it * 64] = vb.w;
        }
        __syncthreads();
#pragma unroll
        for (int kk = 0; kk < 16; kk++) {
            float af[8], bf[8];
            *(float4*)&af[0] = *(const float4*)&As[kk][ty * 8];
            *(float4*)&af[4] = *(const float4*)&As[kk][ty * 8 + 4];
            *(float4*)&bf[0] = *(const float4*)&Bs[kk][tx * 8];
            *(float4*)&bf[4] = *(const float4*)&Bs[kk][tx * 8 + 4];
#pragma unroll
            for (int i = 0; i < 8; i++)
#pragma unroll
                for (int j = 0; j < 8; j++)
                    acc[i][j] = fmaf(af[i], bf[j], acc[i][j]);
        }
        __syncthreads();
    }

#pragma unroll
    for (int i = 0; i < 8; i++) {
        int r = m0 + ty * 8 + i;
        int bb = r >> 12;
        int nn = r & (NC - 1);
#pragma unroll
        for (int j = 0; j < 8; j++) {
            int c = n0 + tx * 8 + j;
            if (EPI == 0) {
                int g = c / 768;
                int rem = c - g * 768;
                int h = rem >> 6, d = rem & 63;
                size_t off = (((size_t)bb * HC + h) * NC + nn) * DC + d;
                float v = acc[i][j];
                if (g == 0) g_Q[off] = v * 0.125f;
                else if (g == 1) g_K[off] = v;
                else g_V[off] = v;
            } else {
                int h = c >> 6, d = c & 63;
                size_t off = (((size_t)bb * HC + h) * NC + nn) * DC + d;
                out[(size_t)r * 768 + c] = acc[i][j] + bias[c] + g_V[off];
            }
        }
    }
}

// ---------------- landmarks: segment means over 64 rows -------------------
__global__ void __launch_bounds__(64) landmarks_kernel()
{
    int bhm = blockIdx.x;           // 0..6143
    int bh = bhm >> 6, m = bhm & 63;
    int d = threadIdx.x;
    size_t base = ((size_t)bh * NC + m * 64) * DC + d;
    float sk = 0.f, sq = 0.f;
#pragma unroll 8
    for (int i = 0; i < 64; i++) {
        sk += g_K[base + (size_t)i * DC];
        sq += g_Q[base + (size_t)i * DC];
    }
    size_t o = ((size_t)bh * MC + m) * DC + d;
    g_Kl[o] = sk * (1.0f / 64.0f);
    g_Ql[o] = sq * (1.0f / 64.0f);
}

// ---------------- kernel2 softmax + Newton-Schulz pinv --------------------
__device__ __forceinline__ void mm64(float* __restrict__ dst,
                                     const float* __restrict__ X,
                                     const float* __restrict__ Y,
                                     int tid, float scale)
{
    __syncthreads();
    int i = tid >> 2, q = tid & 3;
    float a_acc[16];
#pragma unroll
    for (int jj = 0; jj < 16; jj++) a_acc[jj] = 0.f;
    const float* Xi = X + i * 65;
#pragma unroll 8
    for (int k = 0; k < 64; k++) {
        float a = Xi[k];
        const float* Yr = Y + k * 65 + q * 16;
#pragma unroll
        for (int jj = 0; jj < 16; jj++) a_acc[jj] = fmaf(a, Yr[jj], a_acc[jj]);
    }
    float* Di = dst + i * 65 + q * 16;
#pragma unroll
    for (int jj = 0; jj < 16; jj++) Di[jj] = a_acc[jj] * scale;
    __syncthreads();
}

__device__ __forceinline__ void cIminus(float* __restrict__ dst, float cval,
                                        const float* __restrict__ A, int tid)
{
    for (int e = tid; e < 4096; e += 256) {
        int i = e >> 6, j = e & 63;
        dst[i * 65 + j] = (i == j ? cval : 0.0f) - A[i * 65 + j];
    }
    __syncthreads();
}

__global__ void __launch_bounds__(256) inv_kernel()
{
    extern __shared__ float sm[];
    float* Ks = sm;                       // kernel2 matrix (const after setup)
    float* bufs[4] = { sm + 4160, sm + 2 * 4160, sm + 3 * 4160, sm + 4 * 4160 };
    __shared__ float cs[64];

    int bh = blockIdx.x, tid = threadIdx.x;
    size_t lb = (size_t)bh * 4096;

    // Ql -> bufs[2], Kl -> bufs[3] (temporary use)
    for (int e = tid; e < 4096; e += 256) {
        bufs[2][(e >> 6) * 65 + (e & 63)] = g_Ql[lb + e];
        bufs[3][(e >> 6) * 65 + (e & 63)] = g_Kl[lb + e];
    }
    __syncthreads();

    // scores + row softmax -> Ks
    {
        int m = tid >> 2, q = tid & 3;
        float s[16];
        float mx = -1e30f;
        const float* qm = bufs[2] + m * 65;
#pragma unroll
        for (int jj = 0; jj < 16; jj++) {
            int l = q * 16 + jj;
            const float* kl = bufs[3] + l * 65;
            float a = 0.f;
#pragma unroll 8
            for (int d = 0; d < 64; d++) a = fmaf(qm[d], kl[d], a);
            s[jj] = a;
            mx = fmaxf(mx, a);
        }
        mx = fmaxf(mx, __shfl_xor_sync(~0u, mx, 1));
        mx = fmaxf(mx, __shfl_xor_sync(~0u, mx, 2));
        float sum = 0.f;
#pragma unroll
        for (int jj = 0; jj < 16; jj++) { s[jj] = __expf(s[jj] - mx); sum += s[jj]; }
        sum += __shfl_xor_sync(~0u, sum, 1);
        sum += __shfl_xor_sync(~0u, sum, 2);
        float is = 1.0f / sum;
#pragma unroll
        for (int jj = 0; jj < 16; jj++) Ks[m * 65 + q * 16 + jj] = s[jj] * is;
    }
    __syncthreads();

    // scale = max_j sum_i K[i][j];  V = K^T / scale
    if (tid < 64) {
        float a = 0.f;
        for (int i2 = 0; i2 < 64; i2++) a += Ks[i2 * 65 + tid];
        cs[tid] = a;
    }
    __syncthreads();
    float scale = cs[0];
    for (int j = 1; j < 64; j++) scale = fmaxf(scale, cs[j]);
    float rs = 1.0f / scale;
    for (int e = tid; e < 4096; e += 256) {
        int i = e >> 6, j = e & 63;
        bufs[0][i * 65 + j] = Ks[j * 65 + i] * rs;
    }
    __syncthreads();

    int vi = 0;
#pragma unroll 1
    for (int it = 0; it < 6; ++it) {
        float* pv = bufs[vi];
        float* f1 = bufs[(vi + 1) & 3];
        float* f2 = bufs[(vi + 2) & 3];
        float* f3 = bufs[(vi + 3) & 3];
        mm64(f1, Ks, pv, tid, 1.0f);      // KV
        cIminus(f2, 7.0f, f1, tid);       // 7I - KV
        mm64(f3, f1, f2, tid, 1.0f);      // KV(7I-KV)
        cIminus(f2, 15.0f, f3, tid);      // 15I - ...
        mm64(f3, f1, f2, tid, 1.0f);      // KV(...)
        cIminus(f2, 13.0f, f3, tid);      // 13I - ...
        mm64(f3, pv, f2, tid, 0.25f);     // Vnew
        vi = (vi + 3) & 3;
    }
    __syncthreads();
    float* pv = bufs[vi];
    for (int e = tid; e < 4096; e += 256)
        g_inv[lb + e] = pv[(e >> 6) * 65 + (e & 63)];
}

// ---------------- kernel3 softmax (online) fused with @V -------------------
// block = (bh, group of 8 landmark rows); streams K,V tiles of 64 rows.
__global__ void __launch_bounds__(256) k3v_kernel()
{
    __shared__ float Kt[64 * 65];
    __shared__ float Vt[64 * 65];
    __shared__ float qls[512];
    __shared__ float sc[512];
    __shared__ float red8[64];
    __shared__ float rmax_s[8], rsum_s[8], fbr[8];

    int bh = blockIdx.x, mg = blockIdx.y;
    int tid = threadIdx.x;
    size_t base = (size_t)bh * NC * DC;

    for (int e = tid; e < 512; e += 256)
        qls[e] = g_Ql[((size_t)bh * MC + mg * 8) * DC + e];
    if (tid < 8) { rmax_s[tid] = -1e30f; rsum_s[tid] = 0.0f; }
    float acc[8];
#pragma unroll
    for (int m = 0; m < 8; m++) acc[m] = 0.f;

    int nl = tid >> 2, q = tid & 3;
    int d = tid & 63, sl = tid >> 6;
    __syncthreads();

    for (int t = 0; t < 64; t++) {
        for (int e = tid; e < 4096; e += 256) {
            int i = e >> 6, j = e & 63;
            Kt[i * 65 + j] = g_K[base + (size_t)t * 4096 + e];
            Vt[i * 65 + j] = g_V[base + (size_t)t * 4096 + e];
        }
        __syncthreads();

        // scores for 8 m's x 64 n's
#pragma unroll
        for (int m = 0; m < 8; m++) {
            float p = 0.f;
            const float* qp = qls + m * 64 + q * 16;
            const float* kp = Kt + nl * 65 + q * 16;
#pragma unroll
            for (int dd = 0; dd < 16; dd++) p = fmaf(qp[dd], kp[dd], p);
            p += __shfl_xor_sync(~0u, p, 1);
            p += __shfl_xor_sync(~0u, p, 2);
            if (q == 0) sc[m * 64 + nl] = p;
        }
        __syncthreads();

        // tile max per m -> online max update
        if (tid < 64) {
            int m = tid >> 3, seg = tid & 7;
            const float* s8 = sc + m * 64 + seg * 8;
            float v = s8[0];
#pragma unroll
            for (int u = 1; u < 8; u++) v = fmaxf(v, s8[u]);
            red8[tid] = v;
        }
        __syncthreads();
        if (tid < 8) {
            float v = red8[tid * 8];
#pragma unroll
            for (int u = 1; u < 8; u++) v = fmaxf(v, red8[tid * 8 + u]);
            float nm = fmaxf(rmax_s[tid], v);
            fbr[tid] = __expf(rmax_s[tid] - nm);
            rmax_s[tid] = nm;
        }
        __syncthreads();

        // exponentiate
        for (int e = tid; e < 512; e += 256) {
            int m = e >> 6;
            sc[e] = __expf(sc[e] - rmax_s[m]);
        }
        __syncthreads();

        // tile sum per m -> online sum update
        if (tid < 64) {
            int m = tid >> 3, seg = tid & 7;
            const float* s8 = sc + m * 64 + seg * 8;
            float v = 0.f;
#pragma unroll
            for (int u = 0; u < 8; u++) v += s8[u];
            red8[tid] = v;
        }
        __syncthreads();
        if (tid < 8) {
            float v = 0.f;
#pragma unroll
            for (int u = 0; u < 8; u++) v += red8[tid * 8 + u];
            rsum_s[tid] = rsum_s[tid] * fbr[tid] + v;
        }

        // accumulate e * V
#pragma unroll
        for (int m = 0; m < 8; m++) {
            float f = fbr[m];
            float a = acc[m] * f;
            const float* sm2 = sc + m * 64 + sl * 16;
#pragma unroll
            for (int k2 = 0; k2 < 16; k2++) {
                int nl2 = sl * 16 + k2;
                a = fmaf(sm2[k2], Vt[nl2 * 65 + d], a);
            }
            acc[m] = a;
        }
        __syncthreads();
    }

    // combine 4 slices per (m,d), divide by sum
    for (int m = 0; m < 8; m++) {
        qls[tid] = acc[m];
        __syncthreads();
        if (tid < 64) {
            float o = qls[tid] + qls[64 + tid] + qls[128 + tid] + qls[192 + tid];
            o /= rsum_s[m];
            g_k3V[((size_t)bh * MC + mg * 8 + m) * DC + tid] = o;
        }
        __syncthreads();
    }
}

// ---------------- kernel1 softmax -> x inv -> x k3V (per Q row) -----------
__global__ void __launch_bounds__(256) k1_fuse_kernel()
{
    extern __shared__ float sm[];
    float* Kls = sm;              // 64x65
    float* invs = sm + 4160;
    float* kvs = sm + 8320;
    __shared__ float Qs[4][64];
    __shared__ float ps[4][64];
    __shared__ float t1s[4][64];
    __shared__ float wred[8];
    __shared__ float wsum[8];

    int bh = blockIdx.x;
    int b = bh / HC, h = bh - b * HC;
    int tid = threadIdx.x;
    size_t lb = (size_t)bh * 4096;

    for (int e = tid; e < 4096; e += 256) {
        int i = e >> 6, j = e & 63;
        Kls[i * 65 + j] = g_Kl[lb + e];
        invs[i * 65 + j] = g_inv[lb + e];
        kvs[i * 65 + j] = g_k3V[lb + e];
    }
    __syncthreads();

    int r = tid >> 6, c = tid & 63;
    int n0 = blockIdx.y * 64;
    for (int bat = 0; bat < 16; bat++) {
        int n = n0 + bat * 4 + r;
        Qs[r][c] = g_Q[((size_t)bh * NC + n) * DC + c];
        __syncthreads();

        // scores: m = c
        float s = 0.f;
        const float* kl = Kls + c * 65;
#pragma unroll 16
        for (int dd = 0; dd < 64; dd++) s = fmaf(Qs[r][dd], kl[dd], s);

        // softmax across the 64 threads of this row (2 warps)
        float mx = s;
#pragma unroll
        for (int o = 16; o; o >>= 1) mx = fmaxf(mx, __shfl_xor_sync(~0u, mx, o));
        int w = tid >> 5;
        if ((tid & 31) == 0) wred[w] = mx;
        __syncthreads();
        mx = fmaxf(wred[r * 2], wred[r * 2 + 1]);
        float e = __expf(s - mx);
        float sum = e;
#pragma unroll
        for (int o = 16; o; o >>= 1) sum += __shfl_xor_sync(~0u, sum, o);
        if ((tid & 31) == 0) wsum[w] = sum;
        __syncthreads();
        sum = wsum[r * 2] + wsum[r * 2 + 1];
        ps[r][c] = e / sum;
        __syncthreads();

        // t1 = p @ inv : j = c
        float t = 0.f;
#pragma unroll 16
        for (int m2 = 0; m2 < 64; m2++) t = fmaf(ps[r][m2], invs[m2 * 65 + c], t);
        t1s[r][c] = t;
        __syncthreads();

        // out = t1 @ k3V : d = c
        float o = 0.f;
#pragma unroll 16
        for (int j2 = 0; j2 < 64; j2++) o = fmaf(t1s[r][j2], kvs[j2 * 65 + c], o);
        g_SV[((size_t)b * NC + n) * CC + h * 64 + c] = o;
        __syncthreads();
    }
}

// ---------------------------- launcher -------------------------------------
extern "C" void kernel_launch(void* const* d_in, const int* in_sizes, int n_in,
                              void* d_out, int out_size)
{
    const float* x      = (const float*)d_in[0];
    const float* w_qkv  = (const float*)d_in[1];
    const float* w_proj = (const float*)d_in[2];
    const float* b_proj = (const float*)d_in[3];
    float* out = (float*)d_out;

    // 1) qkv GEMM with scatter epilogue
    sgemm_kernel<0><<<dim3(2304 / 128, 32768 / 128), 256>>>(x, w_qkv, nullptr, nullptr);

    // 2) landmarks
    landmarks_kernel<<<BHC * MC, 64>>>();

    // 3) kernel2 softmax + Newton-Schulz pinv (83.2 KB dynamic smem)
    cudaFuncSetAttribute(inv_kernel, cudaFuncAttributeMaxDynamicSharedMemorySize, 5 * 4160 * 4);
    inv_kernel<<<BHC, 256, 5 * 4160 * 4>>>();

    // 4) kernel3 online-softmax fused with @V
    k3v_kernel<<<dim3(BHC, 8), 256>>>();

    // 5) kernel1 softmax x inv x k3V
    cudaFuncSetAttribute(k1_fuse_kernel, cudaFuncAttributeMaxDynamicSharedMemorySize, 3 * 4160 * 4);
    k1_fuse_kernel<<<dim3(BHC, 64), 256, 3 * 4160 * 4>>>();

    // 6) proj GEMM + bias + residual V
    sgemm_kernel<1><<<dim3(768 / 128, 32768 / 128), 256>>>(nullptr, w_proj, out, b_proj);
}

// round 3
// speedup vs baseline: 1.0010x; 1.0010x over previous
#include <cuda_runtime.h>
#include <math.h>
#include <stdint.h>

#define BC 8
#define NC 4096
#define CC 768
#define HC 12
#define DC 64
#define MC 64
#define BHC (BC*HC)

// ---------------- scratch (device globals; no allocation) ----------------
__device__ float g_Q[(size_t)BHC*NC*DC];     // [B,H,N,D], pre-scaled by 1/sqrt(D)
__device__ float g_K[(size_t)BHC*NC*DC];
__device__ float g_V[(size_t)BHC*NC*DC];
__device__ float g_Kl[(size_t)BHC*MC*DC];    // landmarks
__device__ float g_Ql[(size_t)BHC*MC*DC];
__device__ float g_inv[(size_t)BHC*MC*MC];   // pinv(kernel2)
__device__ float g_k3V[(size_t)BHC*MC*DC];   // kernel3 @ V
__device__ float g_SV[(size_t)BC*NC*CC];     // [B,N,C]

// ---------------- SGEMM 128x128x16, C = A * B^T (B row-major [n,k]) ------
// EPI==0: qkv (out/bias unused, scatter into g_Q/g_K/g_V)
// EPI==1: proj (A ignored, reads g_SV; adds bias + permuted V)
template<int EPI>
__global__ void __launch_bounds__(256, 2) sgemm_kernel(
    const float* __restrict__ A, const float* __restrict__ Bm,
    float* __restrict__ out, const float* __restrict__ bias)
{
    __shared__ float As[16][132];
    __shared__ float Bs[16][132];
    const float* Abase = (EPI == 1) ? (const float*)g_SV : A;
    int tid = threadIdx.x;
    int n0 = blockIdx.x * 128;
    int m0 = blockIdx.y * 128;
    int tx = tid & 15, ty = tid >> 4;
    int lrow = tid >> 2;
    int lcol = (tid & 3) << 2;

    float acc[8][8];
#pragma unroll
    for (int i = 0; i < 8; i++)
#pragma unroll
        for (int j = 0; j < 8; j++) acc[i][j] = 0.f;

    const float* Ap = Abase + (size_t)(m0 + lrow) * 768 + lcol;
    const float* Bp = Bm + (size_t)(n0 + lrow) * 768 + lcol;

    for (int k0 = 0; k0 < 768; k0 += 16) {
#pragma unroll
        for (int it = 0; it < 2; it++) {
            float4 va = *(const float4*)(Ap + (size_t)it * 64 * 768 + k0);
            As[lcol + 0][lrow + it * 64] = va.x;
            As[lcol + 1][lrow + it * 64] = va.y;
            As[lcol + 2][lrow + it * 64] = va.z;
            As[lcol + 3][lrow + it * 64] = va.w;
            float4 vb = *(const float4*)(Bp + (size_t)it * 64 * 768 + k0);
            Bs[lcol + 0][lrow + it * 64] = vb.x;
            Bs[lcol + 1][lrow + it * 64] = vb.y;
            Bs[lcol + 2][lrow + it * 64] = vb.z;
            Bs[lcol + 3][lrow + it * 64] = vb.w;
        }
        __syncthreads();
#pragma unroll
        for (int kk = 0; kk < 16; kk++) {
            float af[8], bf[8];
            *(float4*)&af[0] = *(const float4*)&As[kk][ty * 8];
            *(float4*)&af[4] = *(const float4*)&As[kk][ty * 8 + 4];
            *(float4*)&bf[0] = *(const float4*)&Bs[kk][tx * 8];
            *(float4*)&bf[4] = *(const float4*)&Bs[kk][tx * 8 + 4];
#pragma unroll
            for (int i = 0; i < 8; i++)
#pragma unroll
                for (int j = 0; j < 8; j++)
                    acc[i][j] = fmaf(af[i], bf[j], acc[i][j]);
        }
        __syncthreads();
    }

#pragma unroll
    for (int i = 0; i < 8; i++) {
        int r = m0 + ty * 8 + i;
        int bb = r >> 12;
        int nn = r & (NC - 1);
#pragma unroll
        for (int j = 0; j < 8; j++) {
            int c = n0 + tx * 8 + j;
            if (EPI == 0) {
                int g = c / 768;
                int rem = c - g * 768;
                int h = rem >> 6, d = rem & 63;
                size_t off = (((size_t)bb * HC + h) * NC + nn) * DC + d;
                float v = acc[i][j];
                if (g == 0) g_Q[off] = v * 0.125f;
                else if (g == 1) g_K[off] = v;
                else g_V[off] = v;
            } else {
                int h = c >> 6, d = c & 63;
                size_t off = (((size_t)bb * HC + h) * NC + nn) * DC + d;
                out[(size_t)r * 768 + c] = acc[i][j] + bias[c] + g_V[off];
            }
        }
    }
}

// ---------------- landmarks: segment means over 64 rows -------------------
__global__ void __launch_bounds__(64) landmarks_kernel()
{
    int bhm = blockIdx.x;           // 0..6143
    int bh = bhm >> 6, m = bhm & 63;
    int d = threadIdx.x;
    size_t base = ((size_t)bh * NC + m * 64) * DC + d;
    float sk = 0.f, sq = 0.f;
#pragma unroll 8
    for (int i = 0; i < 64; i++) {
        sk += g_K[base + (size_t)i * DC];
        sq += g_Q[base + (size_t)i * DC];
    }
    size_t o = ((size_t)bh * MC + m) * DC + d;
    g_Kl[o] = sk * (1.0f / 64.0f);
    g_Ql[o] = sq * (1.0f / 64.0f);
}

// ---------------- kernel2 softmax + Newton-Schulz pinv --------------------
__device__ __forceinline__ void mm64(float* __restrict__ dst,
                                     const float* __restrict__ X,
                                     const float* __restrict__ Y,
                                     int tid, float scale)
{
    __syncthreads();
    int i = tid >> 2, q = tid & 3;
    float a_acc[16];
#pragma unroll
    for (int jj = 0; jj < 16; jj++) a_acc[jj] = 0.f;
    const float* Xi = X + i * 65;
#pragma unroll 8
    for (int k = 0; k < 64; k++) {
        float a = Xi[k];
        const float* Yr = Y + k * 65 + q * 16;
#pragma unroll
        for (int jj = 0; jj < 16; jj++) a_acc[jj] = fmaf(a, Yr[jj], a_acc[jj]);
    }
    float* Di = dst + i * 65 + q * 16;
#pragma unroll
    for (int jj = 0; jj < 16; jj++) Di[jj] = a_acc[jj] * scale;
    __syncthreads();
}

__device__ __forceinline__ void cIminus(float* __restrict__ dst, float cval,
                                        const float* __restrict__ A, int tid)
{
    for (int e = tid; e < 4096; e += 256) {
        int i = e >> 6, j = e & 63;
        dst[i * 65 + j] = (i == j ? cval : 0.0f) - A[i * 65 + j];
    }
    __syncthreads();
}

__global__ void __launch_bounds__(256) inv_kernel()
{
    extern __shared__ float sm[];
    float* Ks = sm;                       // kernel2 matrix (const after setup)
    float* bufs[4] = { sm + 4160, sm + 2 * 4160, sm + 3 * 4160, sm + 4 * 4160 };
    __shared__ float cs[64];

    int bh = blockIdx.x, tid = threadIdx.x;
    size_t lb = (size_t)bh * 4096;

    // Ql -> bufs[2], Kl -> bufs[3] (temporary use)
    for (int e = tid; e < 4096; e += 256) {
        bufs[2][(e >> 6) * 65 + (e & 63)] = g_Ql[lb + e];
        bufs[3][(e >> 6) * 65 + (e & 63)] = g_Kl[lb + e];
    }
    __syncthreads();

    // scores + row softmax -> Ks
    {
        int m = tid >> 2, q = tid & 3;
        float s[16];
        float mx = -1e30f;
        const float* qm = bufs[2] + m * 65;
#pragma unroll
        for (int jj = 0; jj < 16; jj++) {
            int l = q * 16 + jj;
            const float* kl = bufs[3] + l * 65;
            float a = 0.f;
#pragma unroll 8
            for (int d = 0; d < 64; d++) a = fmaf(qm[d], kl[d], a);
            s[jj] = a;
            mx = fmaxf(mx, a);
        }
        mx = fmaxf(mx, __shfl_xor_sync(~0u, mx, 1));
        mx = fmaxf(mx, __shfl_xor_sync(~0u, mx, 2));
        float sum = 0.f;
#pragma unroll
        for (int jj = 0; jj < 16; jj++) { s[jj] = __expf(s[jj] - mx); sum += s[jj]; }
        sum += __shfl_xor_sync(~0u, sum, 1);
        sum += __shfl_xor_sync(~0u, sum, 2);
        float is = 1.0f / sum;
#pragma unroll
        for (int jj = 0; jj < 16; jj++) Ks[m * 65 + q * 16 + jj] = s[jj] * is;
    }
    __syncthreads();

    // scale = max_j sum_i K[i][j];  V = K^T / scale
    if (tid < 64) {
        float a = 0.f;
        for (int i2 = 0; i2 < 64; i2++) a += Ks[i2 * 65 + tid];
        cs[tid] = a;
    }
    __syncthreads();
    float scale = cs[0];
    for (int j = 1; j < 64; j++) scale = fmaxf(scale, cs[j]);
    float rs = 1.0f / scale;
    for (int e = tid; e < 4096; e += 256) {
        int i = e >> 6, j = e & 63;
        bufs[0][i * 65 + j] = Ks[j * 65 + i] * rs;
    }
    __syncthreads();

    int vi = 0;
#pragma unroll 1
    for (int it = 0; it < 6; ++it) {
        float* pv = bufs[vi];
        float* f1 = bufs[(vi + 1) & 3];
        float* f2 = bufs[(vi + 2) & 3];
        float* f3 = bufs[(vi + 3) & 3];
        mm64(f1, Ks, pv, tid, 1.0f);      // KV
        cIminus(f2, 7.0f, f1, tid);       // 7I - KV
        mm64(f3, f1, f2, tid, 1.0f);      // KV(7I-KV)
        cIminus(f2, 15.0f, f3, tid);      // 15I - ...
        mm64(f3, f1, f2, tid, 1.0f);      // KV(...)
        cIminus(f2, 13.0f, f3, tid);      // 13I - ...
        mm64(f3, pv, f2, tid, 0.25f);     // Vnew
        vi = (vi + 3) & 3;
    }
    __syncthreads();
    float* pv = bufs[vi];
    for (int e = tid; e < 4096; e += 256)
        g_inv[lb + e] = pv[(e >> 6) * 65 + (e & 63)];
}

// ---------------- kernel3 softmax (online) fused with @V -------------------
// block = (bh, group of 8 landmark rows); streams K,V tiles of 64 rows.
__global__ void __launch_bounds__(256) k3v_kernel()
{
    __shared__ float Kt[64 * 65];
    __shared__ float Vt[64 * 65];
    __shared__ float qls[512];
    __shared__ float sc[512];
    __shared__ float red8[64];
    __shared__ float rmax_s[8], rsum_s[8], fbr[8];

    int bh = blockIdx.x, mg = blockIdx.y;
    int tid = threadIdx.x;
    size_t base = (size_t)bh * NC * DC;

    for (int e = tid; e < 512; e += 256)
        qls[e] = g_Ql[((size_t)bh * MC + mg * 8) * DC + e];
    if (tid < 8) { rmax_s[tid] = -1e30f; rsum_s[tid] = 0.0f; }
    float acc[8];
#pragma unroll
    for (int m = 0; m < 8; m++) acc[m] = 0.f;

    int nl = tid >> 2, q = tid & 3;
    int d = tid & 63, sl = tid >> 6;
    __syncthreads();

    for (int t = 0; t < 64; t++) {
        for (int e = tid; e < 4096; e += 256) {
            int i = e >> 6, j = e & 63;
            Kt[i * 65 + j] = g_K[base + (size_t)t * 4096 + e];
            Vt[i * 65 + j] = g_V[base + (size_t)t * 4096 + e];
        }
        __syncthreads();

        // scores for 8 m's x 64 n's
#pragma unroll
        for (int m = 0; m < 8; m++) {
            float p = 0.f;
            const float* qp = qls + m * 64 + q * 16;
            const float* kp = Kt + nl * 65 + q * 16;
#pragma unroll
            for (int dd = 0; dd < 16; dd++) p = fmaf(qp[dd], kp[dd], p);
            p += __shfl_xor_sync(~0u, p, 1);
            p += __shfl_xor_sync(~0u, p, 2);
            if (q == 0) sc[m * 64 + nl] = p;
        }
        __syncthreads();

        // tile max per m -> online max update
        if (tid < 64) {
            int m = tid >> 3, seg = tid & 7;
            const float* s8 = sc + m * 64 + seg * 8;
            float v = s8[0];
#pragma unroll
            for (int u = 1; u < 8; u++) v = fmaxf(v, s8[u]);
            red8[tid] = v;
        }
        __syncthreads();
        if (tid < 8) {
            float v = red8[tid * 8];
#pragma unroll
            for (int u = 1; u < 8; u++) v = fmaxf(v, red8[tid * 8 + u]);
            float nm = fmaxf(rmax_s[tid], v);
            fbr[tid] = __expf(rmax_s[tid] - nm);
            rmax_s[tid] = nm;
        }
        __syncthreads();

        // exponentiate
        for (int e = tid; e < 512; e += 256) {
            int m = e >> 6;
            sc[e] = __expf(sc[e] - rmax_s[m]);
        }
        __syncthreads();

        // tile sum per m -> online sum update
        if (tid < 64) {
            int m = tid >> 3, seg = tid & 7;
            const float* s8 = sc + m * 64 + seg * 8;
            float v = 0.f;
#pragma unroll
            for (int u = 0; u < 8; u++) v += s8[u];
            red8[tid] = v;
        }
        __syncthreads();
        if (tid < 8) {
            float v = 0.f;
#pragma unroll
            for (int u = 0; u < 8; u++) v += red8[tid * 8 + u];
            rsum_s[tid] = rsum_s[tid] * fbr[tid] + v;
        }

        // accumulate e * V
#pragma unroll
        for (int m = 0; m < 8; m++) {
            float f = fbr[m];
            float a = acc[m] * f;
            const float* sm2 = sc + m * 64 + sl * 16;
#pragma unroll
            for (int k2 = 0; k2 < 16; k2++) {
                int nl2 = sl * 16 + k2;
                a = fmaf(sm2[k2], Vt[nl2 * 65 + d], a);
            }
            acc[m] = a;
        }
        __syncthreads();
    }

    // combine 4 slices per (m,d), divide by sum
    for (int m = 0; m < 8; m++) {
        qls[tid] = acc[m];
        __syncthreads();
        if (tid < 64) {
            float o = qls[tid] + qls[64 + tid] + qls[128 + tid] + qls[192 + tid];
            o /= rsum_s[m];
            g_k3V[((size_t)bh * MC + mg * 8 + m) * DC + tid] = o;
        }
        __syncthreads();
    }
}

// ---------------- kernel1 softmax -> x inv -> x k3V (per Q row) -----------
__global__ void __launch_bounds__(256) k1_fuse_kernel()
{
    extern __shared__ float sm[];
    float* Kls = sm;              // 64x65
    float* invs = sm + 4160;
    float* kvs = sm + 8320;
    __shared__ float Qs[4][64];
    __shared__ float ps[4][64];
    __shared__ float t1s[4][64];
    __shared__ float wred[8];
    __shared__ float wsum[8];

    int bh = blockIdx.x;
    int b = bh / HC, h = bh - b * HC;
    int tid = threadIdx.x;
    size_t lb = (size_t)bh * 4096;

    for (int e = tid; e < 4096; e += 256) {
        int i = e >> 6, j = e & 63;
        Kls[i * 65 + j] = g_Kl[lb + e];
        invs[i * 65 + j] = g_inv[lb + e];
        kvs[i * 65 + j] = g_k3V[lb + e];
    }
    __syncthreads();

    int r = tid >> 6, c = tid & 63;
    int n0 = blockIdx.y * 64;
    for (int bat = 0; bat < 16; bat++) {
        int n = n0 + bat * 4 + r;
        Qs[r][c] = g_Q[((size_t)bh * NC + n) * DC + c];
        __syncthreads();

        // scores: m = c
        float s = 0.f;
        const float* kl = Kls + c * 65;
#pragma unroll 16
        for (int dd = 0; dd < 64; dd++) s = fmaf(Qs[r][dd], kl[dd], s);

        // softmax across the 64 threads of this row (2 warps)
        float mx = s;
#pragma unroll
        for (int o = 16; o; o >>= 1) mx = fmaxf(mx, __shfl_xor_sync(~0u, mx, o));
        int w = tid >> 5;
        if ((tid & 31) == 0) wred[w] = mx;
        __syncthreads();
        mx = fmaxf(wred[r * 2], wred[r * 2 + 1]);
        float e = __expf(s - mx);
        float sum = e;
#pragma unroll
        for (int o = 16; o; o >>= 1) sum += __shfl_xor_sync(~0u, sum, o);
        if ((tid & 31) == 0) wsum[w] = sum;
        __syncthreads();
        sum = wsum[r * 2] + wsum[r * 2 + 1];
        ps[r][c] = e / sum;
        __syncthreads();

        // t1 = p @ inv : j = c
        float t = 0.f;
#pragma unroll 16
        for (int m2 = 0; m2 < 64; m2++) t = fmaf(ps[r][m2], invs[m2 * 65 + c], t);
        t1s[r][c] = t;
        __syncthreads();

        // out = t1 @ k3V : d = c
        float o = 0.f;
#pragma unroll 16
        for (int j2 = 0; j2 < 64; j2++) o = fmaf(t1s[r][j2], kvs[j2 * 65 + c], o);
        g_SV[((size_t)b * NC + n) * CC + h * 64 + c] = o;
        __syncthreads();
    }
}

// ---------------------------- launcher -------------------------------------
extern "C" void kernel_launch(void* const* d_in, const int* in_sizes, int n_in,
                              void* d_out, int out_size)
{
    const float* x      = (const float*)d_in[0];
    const float* w_qkv  = (const float*)d_in[1];
    const float* w_proj = (const float*)d_in[2];
    const float* b_proj = (const float*)d_in[3];
    float* out = (float*)d_out;

    // 1) qkv GEMM with scatter epilogue
    sgemm_kernel<0><<<dim3(2304 / 128, 32768 / 128), 256>>>(x, w_qkv, nullptr, nullptr);

    // 2) landmarks
    landmarks_kernel<<<BHC * MC, 64>>>();

    // 3) kernel2 softmax + Newton-Schulz pinv (83.2 KB dynamic smem)
    cudaFuncSetAttribute(inv_kernel, cudaFuncAttributeMaxDynamicSharedMemorySize, 5 * 4160 * 4);
    inv_kernel<<<BHC, 256, 5 * 4160 * 4>>>();

    // 4) kernel3 online-softmax fused with @V
    k3v_kernel<<<dim3(BHC, 8), 256>>>();

    // 5) kernel1 softmax x inv x k3V
    cudaFuncSetAttribute(k1_fuse_kernel, cudaFuncAttributeMaxDynamicSharedMemorySize, 3 * 4160 * 4);
    k1_fuse_kernel<<<dim3(BHC, 64), 256, 3 * 4160 * 4>>>();

    // 6) proj GEMM + bias + residual V
    sgemm_kernel<1><<<dim3(768 / 128, 32768 / 128), 256>>>(nullptr, w_proj, out, b_proj);
}

// round 5
// speedup vs baseline: 2.2938x; 2.2914x over previous
#include <cuda_runtime.h>
#include <math.h>
#include <stdint.h>

#define BC 8
#define NC 4096
#define CC 768
#define HC 12
#define DC 64
#define MC 64
#define BHC (BC*HC)

__device__ float g_Q[(size_t)BHC*NC*DC];
__device__ float g_K[(size_t)BHC*NC*DC];
__device__ float g_V[(size_t)BHC*NC*DC];
__device__ float g_Kl[(size_t)BHC*MC*DC];
__device__ float g_Ql[(size_t)BHC*MC*DC];
__device__ float g_inv[(size_t)BHC*MC*MC];
__device__ float g_k3V[(size_t)BHC*MC*DC];
__device__ float g_SV[(size_t)BC*NC*CC];

// ===================== helpers =====================
__device__ __forceinline__ uint32_t smem_u32(const void* p) {
    uint32_t a;
    asm("{ .reg .u64 t; cvta.to.shared.u64 t, %1; cvt.u32.u64 %0, t; }" : "=r"(a) : "l"(p));
    return a;
}
__device__ __forceinline__ uint32_t f2tf(float f) {
    uint32_t u;
    asm("cvt.rna.tf32.f32 %0, %1;" : "=r"(u) : "f"(f));
    return u;
}
__device__ __forceinline__ void mma_tf32(float* c, const uint32_t* a, const uint32_t* b) {
    asm volatile(
        "mma.sync.aligned.m16n8k8.row.col.f32.tf32.tf32.f32 "
        "{%0,%1,%2,%3}, {%4,%5,%6,%7}, {%8,%9}, {%0,%1,%2,%3};"
        : "+f"(c[0]), "+f"(c[1]), "+f"(c[2]), "+f"(c[3])
        : "r"(a[0]), "r"(a[1]), "r"(a[2]), "r"(a[3]), "r"(b[0]), "r"(b[1]));
}
__device__ __forceinline__ void cp16(uint32_t s, const void* g) {
    asm volatile("cp.async.cg.shared.global [%0], [%1], 16;" :: "r"(s), "l"(g));
}

// ============ mma.sync tf32 GEMM: C[128x128] = A * B^T ====================
// EPI==0: qkv scatter into g_Q(x0.125)/g_K/g_V.  EPI==1: proj + bias + V-resid.
// smem: buf0 A(4608f)+B(4608f), buf1 same = 18432 floats; epilogue reuses.
template<int EPI>
__global__ void __launch_bounds__(256) mma_gemm(
    const float* __restrict__ A, const float* __restrict__ Bm,
    float* __restrict__ out, const float* __restrict__ bias)
{
    extern __shared__ float gs[];
    const float* Abase = (EPI == 1) ? (const float*)g_SV : A;
    int tid = threadIdx.x, lane = tid & 31, wid = tid >> 5;
    int warp_m = wid & 3, warp_n = wid >> 2;
    int n0 = blockIdx.x * 128, m0 = blockIdx.y * 128;
    const float* Ap = Abase + (size_t)m0 * 768;
    const float* Bp = Bm + (size_t)n0 * 768;
    uint32_t sbase = smem_u32(gs);

    float acc[2][8][4];
#pragma unroll
    for (int mt = 0; mt < 2; mt++)
#pragma unroll
        for (int nt = 0; nt < 8; nt++)
#pragma unroll
            for (int u = 0; u < 4; u++) acc[mt][nt][u] = 0.f;

    int prow = tid >> 3, pkg = (tid & 7) * 4;   // cp.async assignment
#define PREFETCH(c, bi) {                                                   \
        int k0 = (c) * 32;                                                  \
        uint32_t ao = sbase + (uint32_t)(bi) * 36864u;                      \
        uint32_t bo = ao + 18432u;                                          \
        _Pragma("unroll")                                                   \
        for (int p = 0; p < 4; p++) {                                       \
            int row = prow + p * 32;                                        \
            uint32_t so = (uint32_t)(row * 36 + pkg) * 4u;                  \
            cp16(ao + so, Ap + (size_t)row * 768 + k0 + pkg);               \
            cp16(bo + so, Bp + (size_t)row * 768 + k0 + pkg);               \
        }                                                                   \
        asm volatile("cp.async.commit_group;" ::: "memory");                \
    }

    PREFETCH(0, 0);
    int gid = lane >> 2, tig = lane & 3;
    for (int c = 0; c < 24; c++) {
        int bi = c & 1;
        asm volatile("cp.async.wait_group 0;" ::: "memory");
        __syncthreads();
        if (c + 1 < 24) PREFETCH(c + 1, bi ^ 1);
        const float* As = gs + bi * 9216;
        const float* Bs = As + 4608;
#pragma unroll
        for (int ks = 0; ks < 4; ks++) {
            int kb = ks * 8 + tig;
            uint32_t af[2][4], bf[8][2];
#pragma unroll
            for (int mt = 0; mt < 2; mt++) {
                int r0 = warp_m * 32 + mt * 16 + gid;
                af[mt][0] = f2tf(As[r0 * 36 + kb]);
                af[mt][1] = f2tf(As[(r0 + 8) * 36 + kb]);
                af[mt][2] = f2tf(As[r0 * 36 + kb + 4]);
                af[mt][3] = f2tf(As[(r0 + 8) * 36 + kb + 4]);
            }
#pragma unroll
            for (int nt = 0; nt < 8; nt++) {
                int c0 = warp_n * 64 + nt * 8 + gid;
                bf[nt][0] = f2tf(Bs[c0 * 36 + kb]);
                bf[nt][1] = f2tf(Bs[c0 * 36 + kb + 4]);
            }
#pragma unroll
            for (int mt = 0; mt < 2; mt++)
#pragma unroll
                for (int nt = 0; nt < 8; nt++)
                    mma_tf32(acc[mt][nt], af[mt], bf[nt]);
        }
        __syncthreads();
    }

    // stage accumulators to smem (stride 130)
#pragma unroll
    for (int mt = 0; mt < 2; mt++)
#pragma unroll
        for (int nt = 0; nt < 8; nt++) {
            int r = warp_m * 32 + mt * 16 + gid;
            int col = warp_n * 64 + nt * 8 + tig * 2;
            *(float2*)(gs + r * 130 + col) = make_float2(acc[mt][nt][0], acc[mt][nt][1]);
            *(float2*)(gs + (r + 8) * 130 + col) = make_float2(acc[mt][nt][2], acc[mt][nt][3]);
        }
    __syncthreads();

    if (EPI == 0) {
        int g = n0 / 768, nb = n0 - g * 768;
        for (int e = tid; e < 16384; e += 256) {
            int row = e >> 7, col = e & 127;
            int r = m0 + row, bb = r >> 12, nn = r & (NC - 1);
            int rem = nb + col, h = rem >> 6, d = rem & 63;
            size_t off = (((size_t)bb * HC + h) * NC + nn) * DC + d;
            float v = gs[row * 130 + col];
            if (g == 0) g_Q[off] = v * 0.125f;
            else if (g == 1) g_K[off] = v;
            else g_V[off] = v;
        }
    } else {
        for (int e = tid; e < 16384; e += 256) {
            int row = e >> 7, col = e & 127;
            int r = m0 + row, c2 = n0 + col;
            int bb = r >> 12, nn = r & (NC - 1);
            int h = c2 >> 6, d = c2 & 63;
            out[(size_t)r * 768 + c2] = gs[row * 130 + col] + bias[c2]
                + g_V[(((size_t)bb * HC + h) * NC + nn) * DC + d];
        }
    }
#undef PREFETCH
}

// ===================== landmarks =====================
__global__ void __launch_bounds__(64) landmarks_kernel()
{
    int bhm = blockIdx.x;
    int bh = bhm >> 6, m = bhm & 63;
    int d = threadIdx.x;
    size_t base = ((size_t)bh * NC + m * 64) * DC + d;
    float sk = 0.f, sq = 0.f;
#pragma unroll 8
    for (int i = 0; i < 64; i++) {
        sk += g_K[base + (size_t)i * DC];
        sq += g_Q[base + (size_t)i * DC];
    }
    size_t o = ((size_t)bh * MC + m) * DC + d;
    g_Kl[o] = sk * (1.0f / 64.0f);
    g_Ql[o] = sq * (1.0f / 64.0f);
}

// ===================== kernel2 softmax + Newton-Schulz =====================
__device__ __forceinline__ void mm64(float* __restrict__ dst, const float* __restrict__ X,
                                     const float* __restrict__ Y, int tid, float scale)
{
    __syncthreads();
    int i = tid >> 2, q = tid & 3;
    float a[16];
#pragma unroll
    for (int j = 0; j < 16; j++) a[j] = 0.f;
    const float* Xi = X + i * 65;
#pragma unroll 8
    for (int k = 0; k < 64; k++) {
        float xv = Xi[k];
        const float* Yr = Y + k * 65 + q * 16;
#pragma unroll
        for (int j = 0; j < 16; j++) a[j] = fmaf(xv, Yr[j], a[j]);
    }
    float* Di = dst + i * 65 + q * 16;
#pragma unroll
    for (int j = 0; j < 16; j++) Di[j] = a[j] * scale;
    __syncthreads();
}
__device__ __forceinline__ void cIminus(float* __restrict__ dst, float cv,
                                        const float* __restrict__ A, int tid)
{
    for (int e = tid; e < 4096; e += 256) {
        int i = e >> 6, j = e & 63;
        dst[i * 65 + j] = (i == j ? cv : 0.0f) - A[i * 65 + j];
    }
    __syncthreads();
}
__global__ void __launch_bounds__(256) inv_kernel()
{
    extern __shared__ float sm[];
    float* Ks = sm;
    float* bufs[4] = { sm + 4160, sm + 2*4160, sm + 3*4160, sm + 4*4160 };
    __shared__ float cs[64];
    int bh = blockIdx.x, tid = threadIdx.x;
    size_t lb = (size_t)bh * 4096;

    for (int e = tid; e < 4096; e += 256) {
        bufs[2][(e >> 6) * 65 + (e & 63)] = g_Ql[lb + e];
        bufs[3][(e >> 6) * 65 + (e & 63)] = g_Kl[lb + e];
    }
    __syncthreads();
    {
        int m = tid >> 2, q = tid & 3;
        float s[16], mx = -1e30f;
        const float* qm = bufs[2] + m * 65;
#pragma unroll
        for (int j = 0; j < 16; j++) {
            const float* kl = bufs[3] + (q * 16 + j) * 65;
            float a = 0.f;
#pragma unroll 8
            for (int d = 0; d < 64; d++) a = fmaf(qm[d], kl[d], a);
            s[j] = a; mx = fmaxf(mx, a);
        }
        mx = fmaxf(mx, __shfl_xor_sync(~0u, mx, 1));
        mx = fmaxf(mx, __shfl_xor_sync(~0u, mx, 2));
        float sum = 0.f;
#pragma unroll
        for (int j = 0; j < 16; j++) { s[j] = __expf(s[j] - mx); sum += s[j]; }
        sum += __shfl_xor_sync(~0u, sum, 1);
        sum += __shfl_xor_sync(~0u, sum, 2);
        float is = 1.0f / sum;
#pragma unroll
        for (int j = 0; j < 16; j++) Ks[m * 65 + q * 16 + j] = s[j] * is;
    }
    __syncthreads();
    if (tid < 64) {
        float a = 0.f;
        for (int i = 0; i < 64; i++) a += Ks[i * 65 + tid];
        cs[tid] = a;
    }
    __syncthreads();
    float sc = cs[0];
    for (int j = 1; j < 64; j++) sc = fmaxf(sc, cs[j]);
    float rs = 1.0f / sc;
    for (int e = tid; e < 4096; e += 256) {
        int i = e >> 6, j = e & 63;
        bufs[0][i * 65 + j] = Ks[j * 65 + i] * rs;
    }
    __syncthreads();
    int vi = 0;
#pragma unroll 1
    for (int it = 0; it < 6; ++it) {
        float* pv = bufs[vi];
        float* f1 = bufs[(vi + 1) & 3];
        float* f2 = bufs[(vi + 2) & 3];
        float* f3 = bufs[(vi + 3) & 3];
        mm64(f1, Ks, pv, tid, 1.0f);
        cIminus(f2, 7.0f, f1, tid);
        mm64(f3, f1, f2, tid, 1.0f);
        cIminus(f2, 15.0f, f3, tid);
        mm64(f3, f1, f2, tid, 1.0f);
        cIminus(f2, 13.0f, f3, tid);
        mm64(f3, pv, f2, tid, 0.25f);
        vi = (vi + 3) & 3;
    }
    __syncthreads();
    float* pv = bufs[vi];
    for (int e = tid; e < 4096; e += 256)
        g_inv[lb + e] = pv[(e >> 6) * 65 + (e & 63)];
}

// ===================== kernel3: online softmax @ V (register tiled) ========
__global__ void __launch_bounds__(256) k3v_kernel()
{
    extern __shared__ float s[];
    float* Qls = s;             // [d][m] stride 68
    float* Kt  = s + 4352;      // [d][n] stride 68
    float* Ps  = s + 8704;      // [n][m] stride 68
    float* Vt  = s + 13056;     // [n][d] stride 64
    int bh = blockIdx.x, tid = threadIdx.x;
    int tm = tid >> 4, tn = tid & 15;
    size_t base = (size_t)bh * NC * DC;

    for (int f = tid; f < 1024; f += 256) {
        int n = f >> 4, dg = (f & 15) * 4;
        float4 v = *(const float4*)(g_Ql + (size_t)bh * 4096 + n * 64 + dg);
        Qls[(dg+0)*68+n] = v.x; Qls[(dg+1)*68+n] = v.y;
        Qls[(dg+2)*68+n] = v.z; Qls[(dg+3)*68+n] = v.w;
    }
    float o[4][4], gmax[4], gsum[4];
#pragma unroll
    for (int i = 0; i < 4; i++) {
        gmax[i] = -1e30f; gsum[i] = 0.f;
#pragma unroll
        for (int j = 0; j < 4; j++) o[i][j] = 0.f;
    }

    for (int t = 0; t < 64; t++) {
        __syncthreads();
        for (int f = tid; f < 1024; f += 256) {
            int n = f >> 4, dg = (f & 15) * 4;
            float4 kv = *(const float4*)(g_K + base + (size_t)t * 4096 + n * 64 + dg);
            Kt[(dg+0)*68+n] = kv.x; Kt[(dg+1)*68+n] = kv.y;
            Kt[(dg+2)*68+n] = kv.z; Kt[(dg+3)*68+n] = kv.w;
            *(float4*)(Vt + n * 64 + dg) =
                *(const float4*)(g_V + base + (size_t)t * 4096 + n * 64 + dg);
        }
        __syncthreads();

        float sc[4][4];
#pragma unroll
        for (int i = 0; i < 4; i++)
#pragma unroll
            for (int j = 0; j < 4; j++) sc[i][j] = 0.f;
#pragma unroll 8
        for (int d = 0; d < 64; d++) {
            float4 q = *(const float4*)(Qls + d * 68 + tm * 4);
            float4 k = *(const float4*)(Kt + d * 68 + tn * 4);
            float qa[4] = {q.x, q.y, q.z, q.w};
            float ka[4] = {k.x, k.y, k.z, k.w};
#pragma unroll
            for (int i = 0; i < 4; i++)
#pragma unroll
                for (int j = 0; j < 4; j++) sc[i][j] = fmaf(qa[i], ka[j], sc[i][j]);
        }
        float fac[4];
#pragma unroll
        for (int i = 0; i < 4; i++) {
            float mx = fmaxf(fmaxf(sc[i][0], sc[i][1]), fmaxf(sc[i][2], sc[i][3]));
            mx = fmaxf(mx, __shfl_xor_sync(~0u, mx, 1));
            mx = fmaxf(mx, __shfl_xor_sync(~0u, mx, 2));
            mx = fmaxf(mx, __shfl_xor_sync(~0u, mx, 4));
            mx = fmaxf(mx, __shfl_xor_sync(~0u, mx, 8));
            float nm = fmaxf(gmax[i], mx);
            fac[i] = __expf(gmax[i] - nm);
            gmax[i] = nm;
            float ts = 0.f;
#pragma unroll
            for (int j = 0; j < 4; j++) {
                float p = __expf(sc[i][j] - nm);
                Ps[(tn * 4 + j) * 68 + tm * 4 + i] = p;
                ts += p;
            }
            ts += __shfl_xor_sync(~0u, ts, 1);
            ts += __shfl_xor_sync(~0u, ts, 2);
            ts += __shfl_xor_sync(~0u, ts, 4);
            ts += __shfl_xor_sync(~0u, ts, 8);
            gsum[i] = gsum[i] * fac[i] + ts;
        }
        __syncthreads();
#pragma unroll
        for (int i = 0; i < 4; i++)
#pragma unroll
            for (int j = 0; j < 4; j++) o[i][j] *= fac[i];
#pragma unroll 8
        for (int n = 0; n < 64; n++) {
            float4 p = *(const float4*)(Ps + n * 68 + tm * 4);
            float4 v = *(const float4*)(Vt + n * 64 + tn * 4);
            float pa[4] = {p.x, p.y, p.z, p.w};
            float va[4] = {v.x, v.y, v.z, v.w};
#pragma unroll
            for (int i = 0; i < 4; i++)
#pragma unroll
                for (int j = 0; j < 4; j++) o[i][j] = fmaf(pa[i], va[j], o[i][j]);
        }
    }
#pragma unroll
    for (int i = 0; i < 4; i++) {
        float inv = 1.0f / gsum[i];
        float4 w = { o[i][0]*inv, o[i][1]*inv, o[i][2]*inv, o[i][3]*inv };
        *(float4*)(g_k3V + ((size_t)bh * MC + tm * 4 + i) * DC + tn * 4) = w;
    }
}

// ===================== kernel1: softmax -> x inv -> x k3V (reg tiled) ======
__global__ void __launch_bounds__(256) k1_kernel()
{
    extern __shared__ float s[];
    float* Qt   = s;                  // [d][n] 68
    float* Kls  = s + 4352;           // [d][m] 68
    float* Ps   = s + 8704;           // [m][n] 68
    float* Ts   = s + 13056;          // [j][n] 68
    float* invs = s + 17408;          // [m][j] 64
    float* kvs  = s + 21504;          // [j][d] 64
    int bh = blockIdx.x, n0 = blockIdx.y * 64;
    int b = bh / HC, h = bh - b * HC;
    int tid = threadIdx.x, tn = tid >> 4, tc = tid & 15;
    size_t qbase = ((size_t)bh * NC + n0) * DC;
    size_t lb = (size_t)bh * 4096;

    for (int f = tid; f < 1024; f += 256) {
        int r = f >> 4, dg = (f & 15) * 4;
        float4 q = *(const float4*)(g_Q + qbase + r * 64 + dg);
        Qt[(dg+0)*68+r] = q.x; Qt[(dg+1)*68+r] = q.y;
        Qt[(dg+2)*68+r] = q.z; Qt[(dg+3)*68+r] = q.w;
        float4 kl = *(const float4*)(g_Kl + lb + r * 64 + dg);
        Kls[(dg+0)*68+r] = kl.x; Kls[(dg+1)*68+r] = kl.y;
        Kls[(dg+2)*68+r] = kl.z; Kls[(dg+3)*68+r] = kl.w;
        *(float4*)(invs + r * 64 + dg) = *(const float4*)(g_inv + lb + r * 64 + dg);
        *(float4*)(kvs + r * 64 + dg)  = *(const float4*)(g_k3V + lb + r * 64 + dg);
    }
    __syncthreads();

    float sc[4][4];
#pragma unroll
    for (int i = 0; i < 4; i++)
#pragma unroll
        for (int j = 0; j < 4; j++) sc[i][j] = 0.f;
#pragma unroll 8
    for (int d = 0; d < 64; d++) {
        float4 q = *(const float4*)(Qt + d * 68 + tn * 4);
        float4 k = *(const float4*)(Kls + d * 68 + tc * 4);
        float qa[4] = {q.x,q.y,q.z,q.w}, ka[4] = {k.x,k.y,k.z,k.w};
#pragma unroll
        for (int i = 0; i < 4; i++)
#pragma unroll
            for (int j = 0; j < 4; j++) sc[i][j] = fmaf(qa[i], ka[j], sc[i][j]);
    }
#pragma unroll
    for (int i = 0; i < 4; i++) {
        float mx = fmaxf(fmaxf(sc[i][0], sc[i][1]), fmaxf(sc[i][2], sc[i][3]));
        mx = fmaxf(mx, __shfl_xor_sync(~0u, mx, 1));
        mx = fmaxf(mx, __shfl_xor_sync(~0u, mx, 2));
        mx = fmaxf(mx, __shfl_xor_sync(~0u, mx, 4));
        mx = fmaxf(mx, __shfl_xor_sync(~0u, mx, 8));
        float p[4], ts = 0.f;
#pragma unroll
        for (int j = 0; j < 4; j++) { p[j] = __expf(sc[i][j] - mx); ts += p[j]; }
        ts += __shfl_xor_sync(~0u, ts, 1);
        ts += __shfl_xor_sync(~0u, ts, 2);
        ts += __shfl_xor_sync(~0u, ts, 4);
        ts += __shfl_xor_sync(~0u, ts, 8);
        float is = 1.0f / ts;
#pragma unroll
        for (int j = 0; j < 4; j++)
            Ps[(tc * 4 + j) * 68 + tn * 4 + i] = p[j] * is;
    }
    __syncthreads();

    float tt[4][4];
#pragma unroll
    for (int i = 0; i < 4; i++)
#pragma unroll
        for (int j = 0; j < 4; j++) tt[i][j] = 0.f;
#pragma unroll 8
    for (int m = 0; m < 64; m++) {
        float4 p = *(const float4*)(Ps + m * 68 + tn * 4);
        float4 iv = *(const float4*)(invs + m * 64 + tc * 4);
        float pa[4] = {p.x,p.y,p.z,p.w}, ia[4] = {iv.x,iv.y,iv.z,iv.w};
#pragma unroll
        for (int i = 0; i < 4; i++)
#pragma unroll
            for (int j = 0; j < 4; j++) tt[i][j] = fmaf(pa[i], ia[j], tt[i][j]);
    }
#pragma unroll
    for (int i = 0; i < 4; i++)
#pragma unroll
        for (int j = 0; j < 4; j++)
            Ts[(tc * 4 + j) * 68 + tn * 4 + i] = tt[i][j];
    __syncthreads();

    float o[4][4];
#pragma unroll
    for (int i = 0; i < 4; i++)
#pragma unroll
        for (int j = 0; j < 4; j++) o[i][j] = 0.f;
#pragma unroll 8
    for (int jj = 0; jj < 64; jj++) {
        float4 t4 = *(const float4*)(Ts + jj * 68 + tn * 4);
        float4 kv = *(const float4*)(kvs + jj * 64 + tc * 4);
        float ta[4] = {t4.x,t4.y,t4.z,t4.w}, ka[4] = {kv.x,kv.y,kv.z,kv.w};
#pragma unroll
        for (int i = 0; i < 4; i++)
#pragma unroll
            for (int j = 0; j < 4; j++) o[i][j] = fmaf(ta[i], ka[j], o[i][j]);
    }
#pragma unroll
    for (int i = 0; i < 4; i++) {
        int n = n0 + tn * 4 + i;
        float4 w = { o[i][0], o[i][1], o[i][2], o[i][3] };
        *(float4*)(g_SV + ((size_t)b * NC + n) * CC + h * 64 + tc * 4) = w;
    }
}

// ===================== launcher =====================
extern "C" void kernel_launch(void* const* d_in, const int* in_sizes, int n_in,
                              void* d_out, int out_size)
{
    (void)in_sizes; (void)n_in; (void)out_size;
    const float* x      = (const float*)d_in[0];
    const float* w_qkv  = (const float*)d_in[1];
    const float* w_proj = (const float*)d_in[2];
    const float* b_proj = (const float*)d_in[3];
    float* out = (float*)d_out;

    cudaFuncSetAttribute(mma_gemm<0>, cudaFuncAttributeMaxDynamicSharedMemorySize, 73728);
    cudaFuncSetAttribute(mma_gemm<1>, cudaFuncAttributeMaxDynamicSharedMemorySize, 73728);
    cudaFuncSetAttribute(inv_kernel, cudaFuncAttributeMaxDynamicSharedMemorySize, 5*4160*4);
    cudaFuncSetAttribute(k3v_kernel, cudaFuncAttributeMaxDynamicSharedMemorySize, 68608);
    cudaFuncSetAttribute(k1_kernel,  cudaFuncAttributeMaxDynamicSharedMemorySize, 102400);

    mma_gemm<0><<<dim3(18, 256), 256, 73728>>>(x, w_qkv, nullptr, nullptr);
    landmarks_kernel<<<BHC * MC, 64>>>();
    inv_kernel<<<BHC, 256, 5*4160*4>>>();
    k3v_kernel<<<BHC, 256, 68608>>>();
    k1_kernel<<<dim3(BHC, 64), 256, 102400>>>();
    mma_gemm<1><<<dim3(6, 256), 256, 73728>>>(nullptr, w_proj, out, b_proj);
}

// round 6
// speedup vs baseline: 2.5501x; 1.1117x over previous
#include <cuda_runtime.h>
#include <math.h>
#include <stdint.h>

#define BC 8
#define NC 4096
#define CC 768
#define HC 12
#define DC 64
#define MC 64
#define BHC (BC*HC)
#define NSPL 4

__device__ float g_Q[(size_t)BHC*NC*DC];
__device__ float g_K[(size_t)BHC*NC*DC];
__device__ float g_V[(size_t)BHC*NC*DC];
__device__ float g_Kl[(size_t)BHC*MC*DC];
__device__ float g_Ql[(size_t)BHC*MC*DC];
__device__ float g_inv[(size_t)BHC*MC*MC];
__device__ float g_k3V[(size_t)BHC*MC*DC];
__device__ float g_SV[(size_t)BC*NC*CC];
__device__ float g_pacc[(size_t)BHC*NSPL*MC*DC];
__device__ float g_pmax[BHC*NSPL*MC];
__device__ float g_psum[BHC*NSPL*MC];

// ===================== helpers =====================
__device__ __forceinline__ uint32_t smem_u32(const void* p) {
    uint32_t a;
    asm("{ .reg .u64 t; cvta.to.shared.u64 t, %1; cvt.u32.u64 %0, t; }" : "=r"(a) : "l"(p));
    return a;
}
__device__ __forceinline__ uint32_t f2tf(float f) {
    uint32_t u;
    asm("cvt.rna.tf32.f32 %0, %1;" : "=r"(u) : "f"(f));
    return u;
}
__device__ __forceinline__ void mma_tf32(float* c, const uint32_t* a, const uint32_t* b) {
    asm volatile(
        "mma.sync.aligned.m16n8k8.row.col.f32.tf32.tf32.f32 "
        "{%0,%1,%2,%3}, {%4,%5,%6,%7}, {%8,%9}, {%0,%1,%2,%3};"
        : "+f"(c[0]), "+f"(c[1]), "+f"(c[2]), "+f"(c[3])
        : "r"(a[0]), "r"(a[1]), "r"(a[2]), "r"(a[3]), "r"(b[0]), "r"(b[1]));
}
__device__ __forceinline__ void cp16(uint32_t s, const void* g) {
    asm volatile("cp.async.cg.shared.global [%0], [%1], 16;" :: "r"(s), "l"(g));
}

// ============ mma.sync tf32 GEMM: C[128x128] = A * B^T ====================
template<int EPI>
__global__ void __launch_bounds__(256) mma_gemm(
    const float* __restrict__ A, const float* __restrict__ Bm,
    float* __restrict__ out, const float* __restrict__ bias)
{
    extern __shared__ float gs[];
    const float* Abase = (EPI == 1) ? (const float*)g_SV : A;
    int tid = threadIdx.x, lane = tid & 31, wid = tid >> 5;
    int warp_m = wid & 3, warp_n = wid >> 2;
    int n0 = blockIdx.x * 128, m0 = blockIdx.y * 128;
    const float* Ap = Abase + (size_t)m0 * 768;
    const float* Bp = Bm + (size_t)n0 * 768;
    uint32_t sbase = smem_u32(gs);

    float acc[2][8][4];
#pragma unroll
    for (int mt = 0; mt < 2; mt++)
#pragma unroll
        for (int nt = 0; nt < 8; nt++)
#pragma unroll
            for (int u = 0; u < 4; u++) acc[mt][nt][u] = 0.f;

    int prow = tid >> 3, pkg = (tid & 7) * 4;
#define PREFETCH(c, bi) {                                                   \
        int k0 = (c) * 32;                                                  \
        uint32_t ao = sbase + (uint32_t)(bi) * 36864u;                      \
        uint32_t bo = ao + 18432u;                                          \
        _Pragma("unroll")                                                   \
        for (int p = 0; p < 4; p++) {                                       \
            int row = prow + p * 32;                                        \
            uint32_t so = (uint32_t)(row * 36 + pkg) * 4u;                  \
            cp16(ao + so, Ap + (size_t)row * 768 + k0 + pkg);               \
            cp16(bo + so, Bp + (size_t)row * 768 + k0 + pkg);               \
        }                                                                   \
        asm volatile("cp.async.commit_group;" ::: "memory");                \
    }

    PREFETCH(0, 0);
    int gid = lane >> 2, tig = lane & 3;
    for (int c = 0; c < 24; c++) {
        int bi = c & 1;
        asm volatile("cp.async.wait_group 0;" ::: "memory");
        __syncthreads();
        if (c + 1 < 24) PREFETCH(c + 1, bi ^ 1);
        const float* As = gs + bi * 9216;
        const float* Bs = As + 4608;
#pragma unroll
        for (int ks = 0; ks < 4; ks++) {
            int kb = ks * 8 + tig;
            uint32_t af[2][4], bf[8][2];
#pragma unroll
            for (int mt = 0; mt < 2; mt++) {
                int r0 = warp_m * 32 + mt * 16 + gid;
                af[mt][0] = f2tf(As[r0 * 36 + kb]);
                af[mt][1] = f2tf(As[(r0 + 8) * 36 + kb]);
                af[mt][2] = f2tf(As[r0 * 36 + kb + 4]);
                af[mt][3] = f2tf(As[(r0 + 8) * 36 + kb + 4]);
            }
#pragma unroll
            for (int nt = 0; nt < 8; nt++) {
                int c0 = warp_n * 64 + nt * 8 + gid;
                bf[nt][0] = f2tf(Bs[c0 * 36 + kb]);
                bf[nt][1] = f2tf(Bs[c0 * 36 + kb + 4]);
            }
#pragma unroll
            for (int mt = 0; mt < 2; mt++)
#pragma unroll
                for (int nt = 0; nt < 8; nt++)
                    mma_tf32(acc[mt][nt], af[mt], bf[nt]);
        }
        __syncthreads();
    }

#pragma unroll
    for (int mt = 0; mt < 2; mt++)
#pragma unroll
        for (int nt = 0; nt < 8; nt++) {
            int r = warp_m * 32 + mt * 16 + gid;
            int col = warp_n * 64 + nt * 8 + tig * 2;
            *(float2*)(gs + r * 130 + col) = make_float2(acc[mt][nt][0], acc[mt][nt][1]);
            *(float2*)(gs + (r + 8) * 130 + col) = make_float2(acc[mt][nt][2], acc[mt][nt][3]);
        }
    __syncthreads();

    if (EPI == 0) {
        int g = n0 / 768, nb = n0 - g * 768;
        for (int e = tid; e < 16384; e += 256) {
            int row = e >> 7, col = e & 127;
            int r = m0 + row, bb = r >> 12, nn = r & (NC - 1);
            int rem = nb + col, h = rem >> 6, d = rem & 63;
            size_t off = (((size_t)bb * HC + h) * NC + nn) * DC + d;
            float v = gs[row * 130 + col];
            if (g == 0) g_Q[off] = v * 0.125f;
            else if (g == 1) g_K[off] = v;
            else g_V[off] = v;
        }
    } else {
        for (int e = tid; e < 16384; e += 256) {
            int row = e >> 7, col = e & 127;
            int r = m0 + row, c2 = n0 + col;
            int bb = r >> 12, nn = r & (NC - 1);
            int h = c2 >> 6, d = c2 & 63;
            out[(size_t)r * 768 + c2] = gs[row * 130 + col] + bias[c2]
                + g_V[(((size_t)bb * HC + h) * NC + nn) * DC + d];
        }
    }
#undef PREFETCH
}

// ===================== landmarks =====================
__global__ void __launch_bounds__(64) landmarks_kernel()
{
    int bhm = blockIdx.x;
    int bh = bhm >> 6, m = bhm & 63;
    int d = threadIdx.x;
    size_t base = ((size_t)bh * NC + m * 64) * DC + d;
    float sk = 0.f, sq = 0.f;
#pragma unroll 8
    for (int i = 0; i < 64; i++) {
        sk += g_K[base + (size_t)i * DC];
        sq += g_Q[base + (size_t)i * DC];
    }
    size_t o = ((size_t)bh * MC + m) * DC + d;
    g_Kl[o] = sk * (1.0f / 64.0f);
    g_Ql[o] = sq * (1.0f / 64.0f);
}

// ===================== kernel2 softmax + Newton-Schulz =====================
// all buffers stride 64; Y-rows read as broadcast float4 (conflict-free)
__device__ __forceinline__ void mm64(float* __restrict__ dst, const float* __restrict__ X,
                                     const float* __restrict__ Y, int tid, float scale)
{
    __syncthreads();
    int i = tid >> 2, q = tid & 3;
    float a[16];
#pragma unroll
    for (int j = 0; j < 16; j++) a[j] = 0.f;
    const float* Xi = X + i * 64;
#pragma unroll
    for (int k = 0; k < 64; k += 4) {
        float4 xv = *(const float4*)(Xi + k);
        float xs[4] = {xv.x, xv.y, xv.z, xv.w};
#pragma unroll
        for (int kk = 0; kk < 4; kk++) {
            const float* Yr = Y + (k + kk) * 64 + q * 16;
            float4 y0 = *(const float4*)(Yr);
            float4 y1 = *(const float4*)(Yr + 4);
            float4 y2 = *(const float4*)(Yr + 8);
            float4 y3 = *(const float4*)(Yr + 12);
            float xk = xs[kk];
            a[0]  = fmaf(xk, y0.x, a[0]);  a[1]  = fmaf(xk, y0.y, a[1]);
            a[2]  = fmaf(xk, y0.z, a[2]);  a[3]  = fmaf(xk, y0.w, a[3]);
            a[4]  = fmaf(xk, y1.x, a[4]);  a[5]  = fmaf(xk, y1.y, a[5]);
            a[6]  = fmaf(xk, y1.z, a[6]);  a[7]  = fmaf(xk, y1.w, a[7]);
            a[8]  = fmaf(xk, y2.x, a[8]);  a[9]  = fmaf(xk, y2.y, a[9]);
            a[10] = fmaf(xk, y2.z, a[10]); a[11] = fmaf(xk, y2.w, a[11]);
            a[12] = fmaf(xk, y3.x, a[12]); a[13] = fmaf(xk, y3.y, a[13]);
            a[14] = fmaf(xk, y3.z, a[14]); a[15] = fmaf(xk, y3.w, a[15]);
        }
    }
    float* Di = dst + i * 64 + q * 16;
#pragma unroll
    for (int j = 0; j < 16; j += 4) {
        float4 w = { a[j]*scale, a[j+1]*scale, a[j+2]*scale, a[j+3]*scale };
        *(float4*)(Di + j) = w;
    }
    __syncthreads();
}
__device__ __forceinline__ void cIminus(float* __restrict__ dst, float cv,
                                        const float* __restrict__ A, int tid)
{
    for (int e = tid; e < 4096; e += 256) {
        int i = e >> 6, j = e & 63;
        dst[e] = (i == j ? cv : 0.0f) - A[e];
    }
    __syncthreads();
}
__global__ void __launch_bounds__(256) inv_kernel()
{
    extern __shared__ float sm[];
    float* Ks = sm;
    float* bufs[4] = { sm + 4096, sm + 2*4096, sm + 3*4096, sm + 4*4096 };
    __shared__ float cs[64];
    int bh = blockIdx.x, tid = threadIdx.x;
    size_t lb = (size_t)bh * 4096;

    for (int e = tid * 4; e < 4096; e += 1024) {
        *(float4*)(bufs[2] + e) = *(const float4*)(g_Ql + lb + e);
        *(float4*)(bufs[3] + e) = *(const float4*)(g_Kl + lb + e);
    }
    __syncthreads();
    {
        int m = tid >> 2, q = tid & 3;
        float s[16], mx = -1e30f;
        const float* qm = bufs[2] + m * 64;
#pragma unroll
        for (int j = 0; j < 16; j++) {
            const float* kl = bufs[3] + (q * 16 + j) * 64;
            float a = 0.f;
#pragma unroll
            for (int d = 0; d < 64; d += 4) {
                float4 qv = *(const float4*)(qm + d);
                float4 kv = *(const float4*)(kl + d);
                a = fmaf(qv.x, kv.x, a); a = fmaf(qv.y, kv.y, a);
                a = fmaf(qv.z, kv.z, a); a = fmaf(qv.w, kv.w, a);
            }
            s[j] = a; mx = fmaxf(mx, a);
        }
        mx = fmaxf(mx, __shfl_xor_sync(~0u, mx, 1));
        mx = fmaxf(mx, __shfl_xor_sync(~0u, mx, 2));
        float sum = 0.f;
#pragma unroll
        for (int j = 0; j < 16; j++) { s[j] = __expf(s[j] - mx); sum += s[j]; }
        sum += __shfl_xor_sync(~0u, sum, 1);
        sum += __shfl_xor_sync(~0u, sum, 2);
        float is = 1.0f / sum;
#pragma unroll
        for (int j = 0; j < 16; j++) Ks[m * 64 + q * 16 + j] = s[j] * is;
    }
    __syncthreads();
    if (tid < 64) {
        float a = 0.f;
        for (int i = 0; i < 64; i++) a += Ks[i * 64 + tid];
        cs[tid] = a;
    }
    __syncthreads();
    float sc = cs[0];
    for (int j = 1; j < 64; j++) sc = fmaxf(sc, cs[j]);
    float rs = 1.0f / sc;
    for (int e = tid; e < 4096; e += 256) {
        int i = e >> 6, j = e & 63;
        bufs[0][e] = Ks[j * 64 + i] * rs;
    }
    __syncthreads();
    int vi = 0;
#pragma unroll 1
    for (int it = 0; it < 6; ++it) {
        float* pv = bufs[vi];
        float* f1 = bufs[(vi + 1) & 3];
        float* f2 = bufs[(vi + 2) & 3];
        float* f3 = bufs[(vi + 3) & 3];
        mm64(f1, Ks, pv, tid, 1.0f);
        cIminus(f2, 7.0f, f1, tid);
        mm64(f3, f1, f2, tid, 1.0f);
        cIminus(f2, 15.0f, f3, tid);
        mm64(f3, f1, f2, tid, 1.0f);
        cIminus(f2, 13.0f, f3, tid);
        mm64(f3, pv, f2, tid, 0.25f);
        vi = (vi + 3) & 3;
    }
    __syncthreads();
    float* pv = bufs[vi];
    for (int e = tid * 4; e < 4096; e += 1024)
        *(float4*)(g_inv + lb + e) = *(const float4*)(pv + e);
}

// ===================== kernel3 part: online softmax @ V over 16 tiles ======
__global__ void __launch_bounds__(256) k3v_part()
{
    extern __shared__ float s[];
    float* Qls = s;             // [d][m] stride 68
    float* Kt  = s + 4352;      // [d][n] stride 68
    float* Ps  = s + 8704;      // [n][m] stride 68
    float* Vt  = s + 13056;     // [n][d] stride 64
    int bh = blockIdx.x, sp = blockIdx.y, tid = threadIdx.x;
    int tm = tid >> 4, tn = tid & 15;
    size_t base = (size_t)bh * NC * DC;

    for (int f = tid; f < 1024; f += 256) {
        int n = f >> 4, dg = (f & 15) * 4;
        float4 v = *(const float4*)(g_Ql + (size_t)bh * 4096 + n * 64 + dg);
        Qls[(dg+0)*68+n] = v.x; Qls[(dg+1)*68+n] = v.y;
        Qls[(dg+2)*68+n] = v.z; Qls[(dg+3)*68+n] = v.w;
    }
    float o[4][4], gmax[4], gsum[4];
#pragma unroll
    for (int i = 0; i < 4; i++) {
        gmax[i] = -1e30f; gsum[i] = 0.f;
#pragma unroll
        for (int j = 0; j < 4; j++) o[i][j] = 0.f;
    }

    for (int t = sp * 16; t < sp * 16 + 16; t++) {
        __syncthreads();
        for (int f = tid; f < 1024; f += 256) {
            int n = f >> 4, dg = (f & 15) * 4;
            float4 kv = *(const float4*)(g_K + base + (size_t)t * 4096 + n * 64 + dg);
            Kt[(dg+0)*68+n] = kv.x; Kt[(dg+1)*68+n] = kv.y;
            Kt[(dg+2)*68+n] = kv.z; Kt[(dg+3)*68+n] = kv.w;
            *(float4*)(Vt + n * 64 + dg) =
                *(const float4*)(g_V + base + (size_t)t * 4096 + n * 64 + dg);
        }
        __syncthreads();

        float sc[4][4];
#pragma unroll
        for (int i = 0; i < 4; i++)
#pragma unroll
            for (int j = 0; j < 4; j++) sc[i][j] = 0.f;
#pragma unroll 8
        for (int d = 0; d < 64; d++) {
            float4 q = *(const float4*)(Qls + d * 68 + tm * 4);
            float4 k = *(const float4*)(Kt + d * 68 + tn * 4);
            float qa[4] = {q.x, q.y, q.z, q.w};
            float ka[4] = {k.x, k.y, k.z, k.w};
#pragma unroll
            for (int i = 0; i < 4; i++)
#pragma unroll
                for (int j = 0; j < 4; j++) sc[i][j] = fmaf(qa[i], ka[j], sc[i][j]);
        }
        float fac[4];
#pragma unroll
        for (int i = 0; i < 4; i++) {
            float mx = fmaxf(fmaxf(sc[i][0], sc[i][1]), fmaxf(sc[i][2], sc[i][3]));
            mx = fmaxf(mx, __shfl_xor_sync(~0u, mx, 1));
            mx = fmaxf(mx, __shfl_xor_sync(~0u, mx, 2));
            mx = fmaxf(mx, __shfl_xor_sync(~0u, mx, 4));
            mx = fmaxf(mx, __shfl_xor_sync(~0u, mx, 8));
            float nm = fmaxf(gmax[i], mx);
            fac[i] = __expf(gmax[i] - nm);
            gmax[i] = nm;
            float ts = 0.f;
#pragma unroll
            for (int j = 0; j < 4; j++) {
                float p = __expf(sc[i][j] - nm);
                Ps[(tn * 4 + j) * 68 + tm * 4 + i] = p;
                ts += p;
            }
            ts += __shfl_xor_sync(~0u, ts, 1);
            ts += __shfl_xor_sync(~0u, ts, 2);
            ts += __shfl_xor_sync(~0u, ts, 4);
            ts += __shfl_xor_sync(~0u, ts, 8);
            gsum[i] = gsum[i] * fac[i] + ts;
        }
        __syncthreads();
#pragma unroll
        for (int i = 0; i < 4; i++)
#pragma unroll
            for (int j = 0; j < 4; j++) o[i][j] *= fac[i];
#pragma unroll 8
        for (int n = 0; n < 64; n++) {
            float4 p = *(const float4*)(Ps + n * 68 + tm * 4);
            float4 v = *(const float4*)(Vt + n * 64 + tn * 4);
            float pa[4] = {p.x, p.y, p.z, p.w};
            float va[4] = {v.x, v.y, v.z, v.w};
#pragma unroll
            for (int i = 0; i < 4; i++)
#pragma unroll
                for (int j = 0; j < 4; j++) o[i][j] = fmaf(pa[i], va[j], o[i][j]);
        }
    }
    size_t pb = ((size_t)bh * NSPL + sp) * 4096;
#pragma unroll
    for (int i = 0; i < 4; i++) {
        float4 w = { o[i][0], o[i][1], o[i][2], o[i][3] };
        *(float4*)(g_pacc + pb + (tm * 4 + i) * 64 + tn * 4) = w;
    }
    if (tn == 0) {
        int mb = (bh * NSPL + sp) * 64 + tm * 4;
#pragma unroll
        for (int i = 0; i < 4; i++) {
            g_pmax[mb + i] = gmax[i];
            g_psum[mb + i] = gsum[i];
        }
    }
}

__global__ void __launch_bounds__(256) k3v_combine()
{
    __shared__ float pm[NSPL*64], ps[NSPL*64], fs[NSPL*64], inv_s[64];
    int bh = blockIdx.x, tid = threadIdx.x;
    pm[tid] = g_pmax[bh * NSPL * 64 + tid];
    ps[tid] = g_psum[bh * NSPL * 64 + tid];
    __syncthreads();
    if (tid < 64) {
        float gm = pm[tid];
#pragma unroll
        for (int s2 = 1; s2 < NSPL; s2++) gm = fmaxf(gm, pm[s2*64+tid]);
        float tot = 0.f;
#pragma unroll
        for (int s2 = 0; s2 < NSPL; s2++) {
            float f = __expf(pm[s2*64+tid] - gm);
            fs[s2*64+tid] = f;
            tot += ps[s2*64+tid] * f;
        }
        inv_s[tid] = 1.0f / tot;
    }
    __syncthreads();
    size_t pb = (size_t)bh * NSPL * 4096;
    for (int e = tid * 4; e < 4096; e += 1024) {
        int m = e >> 6;
        float4 o = make_float4(0.f, 0.f, 0.f, 0.f);
#pragma unroll
        for (int s2 = 0; s2 < NSPL; s2++) {
            float f = fs[s2*64+m];
            float4 a = *(const float4*)(g_pacc + pb + s2*4096 + e);
            o.x = fmaf(a.x, f, o.x); o.y = fmaf(a.y, f, o.y);
            o.z = fmaf(a.z, f, o.z); o.w = fmaf(a.w, f, o.w);
        }
        float iv = inv_s[m];
        o.x *= iv; o.y *= iv; o.z *= iv; o.w *= iv;
        *(float4*)(g_k3V + (size_t)bh * 4096 + e) = o;
    }
}

// ===================== kernel1: softmax -> x inv -> x k3V (reg tiled) ======
__global__ void __launch_bounds__(256) k1_kernel()
{
    extern __shared__ float s[];
    float* Qt   = s;                  // [d][n] 68
    float* Kls  = s + 4352;           // [d][m] 68
    float* Ps   = s + 8704;           // [m][n] 68
    float* Ts   = s + 13056;          // [j][n] 68
    float* invs = s + 17408;          // [m][j] 64
    float* kvs  = s + 21504;          // [j][d] 64
    int bh = blockIdx.x, n0 = blockIdx.y * 64;
    int b = bh / HC, h = bh - b * HC;
    int tid = threadIdx.x, tn = tid >> 4, tc = tid & 15;
    size_t qbase = ((size_t)bh * NC + n0) * DC;
    size_t lb = (size_t)bh * 4096;

    for (int f = tid; f < 1024; f += 256) {
        int r = f >> 4, dg = (f & 15) * 4;
        float4 q = *(const float4*)(g_Q + qbase + r * 64 + dg);
        Qt[(dg+0)*68+r] = q.x; Qt[(dg+1)*68+r] = q.y;
        Qt[(dg+2)*68+r] = q.z; Qt[(dg+3)*68+r] = q.w;
        float4 kl = *(const float4*)(g_Kl + lb + r * 64 + dg);
        Kls[(dg+0)*68+r] = kl.x; Kls[(dg+1)*68+r] = kl.y;
        Kls[(dg+2)*68+r] = kl.z; Kls[(dg+3)*68+r] = kl.w;
        *(float4*)(invs + r * 64 + dg) = *(const float4*)(g_inv + lb + r * 64 + dg);
        *(float4*)(kvs + r * 64 + dg)  = *(const float4*)(g_k3V + lb + r * 64 + dg);
    }
    __syncthreads();

    float sc[4][4];
#pragma unroll
    for (int i = 0; i < 4; i++)
#pragma unroll
        for (int j = 0; j < 4; j++) sc[i][j] = 0.f;
#pragma unroll 8
    for (int d = 0; d < 64; d++) {
        float4 q = *(const float4*)(Qt + d * 68 + tn * 4);
        float4 k = *(const float4*)(Kls + d * 68 + tc * 4);
        float qa[4] = {q.x,q.y,q.z,q.w}, ka[4] = {k.x,k.y,k.z,k.w};
#pragma unroll
        for (int i = 0; i < 4; i++)
#pragma unroll
            for (int j = 0; j < 4; j++) sc[i][j] = fmaf(qa[i], ka[j], sc[i][j]);
    }
#pragma unroll
    for (int i = 0; i < 4; i++) {
        float mx = fmaxf(fmaxf(sc[i][0], sc[i][1]), fmaxf(sc[i][2], sc[i][3]));
        mx = fmaxf(mx, __shfl_xor_sync(~0u, mx, 1));
        mx = fmaxf(mx, __shfl_xor_sync(~0u, mx, 2));
        mx = fmaxf(mx, __shfl_xor_sync(~0u, mx, 4));
        mx = fmaxf(mx, __shfl_xor_sync(~0u, mx, 8));
        float p[4], ts = 0.f;
#pragma unroll
        for (int j = 0; j < 4; j++) { p[j] = __expf(sc[i][j] - mx); ts += p[j]; }
        ts += __shfl_xor_sync(~0u, ts, 1);
        ts += __shfl_xor_sync(~0u, ts, 2);
        ts += __shfl_xor_sync(~0u, ts, 4);
        ts += __shfl_xor_sync(~0u, ts, 8);
        float is = 1.0f / ts;
#pragma unroll
        for (int j = 0; j < 4; j++)
            Ps[(tc * 4 + j) * 68 + tn * 4 + i] = p[j] * is;
    }
    __syncthreads();

    float tt[4][4];
#pragma unroll
    for (int i = 0; i < 4; i++)
#pragma unroll
        for (int j = 0; j < 4; j++) tt[i][j] = 0.f;
#pragma unroll 8
    for (int m = 0; m < 64; m++) {
        float4 p = *(const float4*)(Ps + m * 68 + tn * 4);
        float4 iv = *(const float4*)(invs + m * 64 + tc * 4);
        float pa[4] = {p.x,p.y,p.z,p.w}, ia[4] = {iv.x,iv.y,iv.z,iv.w};
#pragma unroll
        for (int i = 0; i < 4; i++)
#pragma unroll
            for (int j = 0; j < 4; j++) tt[i][j] = fmaf(pa[i], ia[j], tt[i][j]);
    }
#pragma unroll
    for (int i = 0; i < 4; i++)
#pragma unroll
        for (int j = 0; j < 4; j++)
            Ts[(tc * 4 + j) * 68 + tn * 4 + i] = tt[i][j];
    __syncthreads();

    float o[4][4];
#pragma unroll
    for (int i = 0; i < 4; i++)
#pragma unroll
        for (int j = 0; j < 4; j++) o[i][j] = 0.f;
#pragma unroll 8
    for (int jj = 0; jj < 64; jj++) {
        float4 t4 = *(const float4*)(Ts + jj * 68 + tn * 4);
        float4 kv = *(const float4*)(kvs + jj * 64 + tc * 4);
        float ta[4] = {t4.x,t4.y,t4.z,t4.w}, ka[4] = {kv.x,kv.y,kv.z,kv.w};
#pragma unroll
        for (int i = 0; i < 4; i++)
#pragma unroll
            for (int j = 0; j < 4; j++) o[i][j] = fmaf(ta[i], ka[j], o[i][j]);
    }
#pragma unroll
    for (int i = 0; i < 4; i++) {
        int n = n0 + tn * 4 + i;
        float4 w = { o[i][0], o[i][1], o[i][2], o[i][3] };
        *(float4*)(g_SV + ((size_t)b * NC + n) * CC + h * 64 + tc * 4) = w;
    }
}

// ===================== launcher =====================
extern "C" void kernel_launch(void* const* d_in, const int* in_sizes, int n_in,
                              void* d_out, int out_size)
{
    (void)in_sizes; (void)n_in; (void)out_size;
    const float* x      = (const float*)d_in[0];
    const float* w_qkv  = (const float*)d_in[1];
    const float* w_proj = (const float*)d_in[2];
    const float* b_proj = (const float*)d_in[3];
    float* out = (float*)d_out;

    cudaFuncSetAttribute(mma_gemm<0>, cudaFuncAttributeMaxDynamicSharedMemorySize, 73728);
    cudaFuncSetAttribute(mma_gemm<1>, cudaFuncAttributeMaxDynamicSharedMemorySize, 73728);
    cudaFuncSetAttribute(inv_kernel, cudaFuncAttributeMaxDynamicSharedMemorySize, 5*4096*4);
    cudaFuncSetAttribute(k3v_part,   cudaFuncAttributeMaxDynamicSharedMemorySize, 68608);
    cudaFuncSetAttribute(k1_kernel,  cudaFuncAttributeMaxDynamicSharedMemorySize, 102400);

    mma_gemm<0><<<dim3(18, 256), 256, 73728>>>(x, w_qkv, nullptr, nullptr);
    landmarks_kernel<<<BHC * MC, 64>>>();
    inv_kernel<<<BHC, 256, 5*4096*4>>>();
    k3v_part<<<dim3(BHC, NSPL), 256, 68608>>>();
    k3v_combine<<<BHC, 256>>>();
    k1_kernel<<<dim3(BHC, 64), 256, 102400>>>();
    mma_gemm<1><<<dim3(6, 256), 256, 73728>>>(nullptr, w_proj, out, b_proj);
}

// round 7
// speedup vs baseline: 2.8130x; 1.1031x over previous
#include <cuda_runtime.h>
#include <math.h>
#include <stdint.h>

#define BC 8
#define NC 4096
#define CC 768
#define HC 12
#define DC 64
#define MC 64
#define BHC (BC*HC)
#define NSPL 8

__device__ float g_Q[(size_t)BHC*NC*DC];
__device__ float g_K[(size_t)BHC*NC*DC];
__device__ float g_V[(size_t)BHC*NC*DC];
__device__ float g_Kl[(size_t)BHC*MC*DC];
__device__ float g_Ql[(size_t)BHC*MC*DC];
__device__ float g_inv[(size_t)BHC*MC*MC];
__device__ float g_k3V[(size_t)BHC*MC*DC];
__device__ float g_SV[(size_t)BC*NC*CC];
__device__ float g_pacc[(size_t)BHC*NSPL*MC*DC];
__device__ float g_psum[BHC*NSPL*MC];

// ===================== helpers =====================
__device__ __forceinline__ uint32_t smem_u32(const void* p) {
    uint32_t a;
    asm("{ .reg .u64 t; cvta.to.shared.u64 t, %1; cvt.u32.u64 %0, t; }" : "=r"(a) : "l"(p));
    return a;
}
__device__ __forceinline__ void mma_tf32(float* c, const uint32_t* a, const uint32_t* b) {
    asm volatile(
        "mma.sync.aligned.m16n8k8.row.col.f32.tf32.tf32.f32 "
        "{%0,%1,%2,%3}, {%4,%5,%6,%7}, {%8,%9}, {%0,%1,%2,%3};"
        : "+f"(c[0]), "+f"(c[1]), "+f"(c[2]), "+f"(c[3])
        : "r"(a[0]), "r"(a[1]), "r"(a[2]), "r"(a[3]), "r"(b[0]), "r"(b[1]));
}
__device__ __forceinline__ void cp16(uint32_t s, const void* g) {
    asm volatile("cp.async.cg.shared.global [%0], [%1], 16;" :: "r"(s), "l"(g));
}
__device__ __forceinline__ uint32_t fbits(float f) { return __float_as_uint(f); }

// ============ mma.sync tf32 GEMM: C[128x128] = A * B^T ====================
template<int EPI>
__global__ void __launch_bounds__(256) mma_gemm(
    const float* __restrict__ A, const float* __restrict__ Bm,
    float* __restrict__ out, const float* __restrict__ bias)
{
    extern __shared__ float gs[];
    const float* Abase = (EPI == 1) ? (const float*)g_SV : A;
    int tid = threadIdx.x, lane = tid & 31, wid = tid >> 5;
    int warp_m = wid & 3, warp_n = wid >> 2;
    int n0 = blockIdx.x * 128, m0 = blockIdx.y * 128;
    const float* Ap = Abase + (size_t)m0 * 768;
    const float* Bp = Bm + (size_t)n0 * 768;
    uint32_t sbase = smem_u32(gs);

    float acc[2][8][4];
#pragma unroll
    for (int mt = 0; mt < 2; mt++)
#pragma unroll
        for (int nt = 0; nt < 8; nt++)
#pragma unroll
            for (int u = 0; u < 4; u++) acc[mt][nt][u] = 0.f;

    int prow = tid >> 3, pkg = (tid & 7) * 4;
#define PREFETCH(c, bi) {                                                   \
        int k0 = (c) * 32;                                                  \
        uint32_t ao = sbase + (uint32_t)(bi) * 36864u;                      \
        uint32_t bo = ao + 18432u;                                          \
        _Pragma("unroll")                                                   \
        for (int p = 0; p < 4; p++) {                                       \
            int row = prow + p * 32;                                        \
            uint32_t so = (uint32_t)(row * 36 + pkg) * 4u;                  \
            cp16(ao + so, Ap + (size_t)row * 768 + k0 + pkg);               \
            cp16(bo + so, Bp + (size_t)row * 768 + k0 + pkg);               \
        }                                                                   \
        asm volatile("cp.async.commit_group;" ::: "memory");                \
    }

    PREFETCH(0, 0);
    int gid = lane >> 2, tig = lane & 3;
    for (int c = 0; c < 24; c++) {
        int bi = c & 1;
        asm volatile("cp.async.wait_group 0;" ::: "memory");
        __syncthreads();
        if (c + 1 < 24) PREFETCH(c + 1, bi ^ 1);
        const float* As = gs + bi * 9216;
        const float* Bs = As + 4608;
#pragma unroll
        for (int ks = 0; ks < 4; ks++) {
            int kb = ks * 8 + tig;
            uint32_t af[2][4], bf[8][2];
#pragma unroll
            for (int mt = 0; mt < 2; mt++) {
                int r0 = warp_m * 32 + mt * 16 + gid;
                af[mt][0] = fbits(As[r0 * 36 + kb]);
                af[mt][1] = fbits(As[(r0 + 8) * 36 + kb]);
                af[mt][2] = fbits(As[r0 * 36 + kb + 4]);
                af[mt][3] = fbits(As[(r0 + 8) * 36 + kb + 4]);
            }
#pragma unroll
            for (int nt = 0; nt < 8; nt++) {
                int c0 = warp_n * 64 + nt * 8 + gid;
                bf[nt][0] = fbits(Bs[c0 * 36 + kb]);
                bf[nt][1] = fbits(Bs[c0 * 36 + kb + 4]);
            }
#pragma unroll
            for (int mt = 0; mt < 2; mt++)
#pragma unroll
                for (int nt = 0; nt < 8; nt++)
                    mma_tf32(acc[mt][nt], af[mt], bf[nt]);
        }
        __syncthreads();
    }

#pragma unroll
    for (int mt = 0; mt < 2; mt++)
#pragma unroll
        for (int nt = 0; nt < 8; nt++) {
            int r = warp_m * 32 + mt * 16 + gid;
            int col = warp_n * 64 + nt * 8 + tig * 2;
            *(float2*)(gs + r * 130 + col) = make_float2(acc[mt][nt][0], acc[mt][nt][1]);
            *(float2*)(gs + (r + 8) * 130 + col) = make_float2(acc[mt][nt][2], acc[mt][nt][3]);
        }
    __syncthreads();

    if (EPI == 0) {
        int g = n0 / 768, nb = n0 - g * 768;
        for (int e = tid; e < 16384; e += 256) {
            int row = e >> 7, col = e & 127;
            int r = m0 + row, bb = r >> 12, nn = r & (NC - 1);
            int rem = nb + col, h = rem >> 6, d = rem & 63;
            size_t off = (((size_t)bb * HC + h) * NC + nn) * DC + d;
            float v = gs[row * 130 + col];
            if (g == 0) g_Q[off] = v * 0.125f;
            else if (g == 1) g_K[off] = v;
            else g_V[off] = v;
        }
    } else {
        for (int e = tid; e < 16384; e += 256) {
            int row = e >> 7, col = e & 127;
            int r = m0 + row, c2 = n0 + col;
            int bb = r >> 12, nn = r & (NC - 1);
            int h = c2 >> 6, d = c2 & 63;
            out[(size_t)r * 768 + c2] = gs[row * 130 + col] + bias[c2]
                + g_V[(((size_t)bb * HC + h) * NC + nn) * DC + d];
        }
    }
#undef PREFETCH
}

// ===================== landmarks =====================
__global__ void __launch_bounds__(64) landmarks_kernel()
{
    int bhm = blockIdx.x;
    int bh = bhm >> 6, m = bhm & 63;
    int d = threadIdx.x;
    size_t base = ((size_t)bh * NC + m * 64) * DC + d;
    float sk = 0.f, sq = 0.f;
#pragma unroll 8
    for (int i = 0; i < 64; i++) {
        sk += g_K[base + (size_t)i * DC];
        sq += g_Q[base + (size_t)i * DC];
    }
    size_t o = ((size_t)bh * MC + m) * DC + d;
    g_Kl[o] = sk * (1.0f / 64.0f);
    g_Ql[o] = sq * (1.0f / 64.0f);
}

// ===================== kernel2 softmax + Newton-Schulz =====================
__device__ __forceinline__ void mm64(float* __restrict__ dst, const float* __restrict__ X,
                                     const float* __restrict__ Y, int tid, float scale)
{
    __syncthreads();
    int i = tid >> 2, q = tid & 3;
    float a[16];
#pragma unroll
    for (int j = 0; j < 16; j++) a[j] = 0.f;
    const float* Xi = X + i * 64;
#pragma unroll
    for (int k = 0; k < 64; k += 4) {
        float4 xv = *(const float4*)(Xi + k);
        float xs[4] = {xv.x, xv.y, xv.z, xv.w};
#pragma unroll
        for (int kk = 0; kk < 4; kk++) {
            const float* Yr = Y + (k + kk) * 64 + q * 16;
            float4 y0 = *(const float4*)(Yr);
            float4 y1 = *(const float4*)(Yr + 4);
            float4 y2 = *(const float4*)(Yr + 8);
            float4 y3 = *(const float4*)(Yr + 12);
            float xk = xs[kk];
            a[0]  = fmaf(xk, y0.x, a[0]);  a[1]  = fmaf(xk, y0.y, a[1]);
            a[2]  = fmaf(xk, y0.z, a[2]);  a[3]  = fmaf(xk, y0.w, a[3]);
            a[4]  = fmaf(xk, y1.x, a[4]);  a[5]  = fmaf(xk, y1.y, a[5]);
            a[6]  = fmaf(xk, y1.z, a[6]);  a[7]  = fmaf(xk, y1.w, a[7]);
            a[8]  = fmaf(xk, y2.x, a[8]);  a[9]  = fmaf(xk, y2.y, a[9]);
            a[10] = fmaf(xk, y2.z, a[10]); a[11] = fmaf(xk, y2.w, a[11]);
            a[12] = fmaf(xk, y3.x, a[12]); a[13] = fmaf(xk, y3.y, a[13]);
            a[14] = fmaf(xk, y3.z, a[14]); a[15] = fmaf(xk, y3.w, a[15]);
        }
    }
    float* Di = dst + i * 64 + q * 16;
#pragma unroll
    for (int j = 0; j < 16; j += 4) {
        float4 w = { a[j]*scale, a[j+1]*scale, a[j+2]*scale, a[j+3]*scale };
        *(float4*)(Di + j) = w;
    }
    __syncthreads();
}
__device__ __forceinline__ void cIminus(float* __restrict__ dst, float cv,
                                        const float* __restrict__ A, int tid)
{
    for (int e = tid; e < 4096; e += 256) {
        int i = e >> 6, j = e & 63;
        dst[e] = (i == j ? cv : 0.0f) - A[e];
    }
    __syncthreads();
}
__global__ void __launch_bounds__(256) inv_kernel()
{
    extern __shared__ float sm[];
    float* Ks = sm;
    float* bufs[4] = { sm + 4096, sm + 2*4096, sm + 3*4096, sm + 4*4096 };
    __shared__ float cs[64];
    int bh = blockIdx.x, tid = threadIdx.x;
    size_t lb = (size_t)bh * 4096;

    for (int e = tid * 4; e < 4096; e += 1024) {
        *(float4*)(bufs[2] + e) = *(const float4*)(g_Ql + lb + e);
        *(float4*)(bufs[3] + e) = *(const float4*)(g_Kl + lb + e);
    }
    __syncthreads();
    {
        int m = tid >> 2, q = tid & 3;
        float s[16];
        const float* qm = bufs[2] + m * 64;
#pragma unroll
        for (int j = 0; j < 16; j++) {
            const float* kl = bufs[3] + (q * 16 + j) * 64;
            float a = 0.f;
#pragma unroll
            for (int d = 0; d < 64; d += 4) {
                float4 qv = *(const float4*)(qm + d);
                float4 kv = *(const float4*)(kl + d);
                a = fmaf(qv.x, kv.x, a); a = fmaf(qv.y, kv.y, a);
                a = fmaf(qv.z, kv.z, a); a = fmaf(qv.w, kv.w, a);
            }
            s[j] = a;
        }
        float sum = 0.f;
#pragma unroll
        for (int j = 0; j < 16; j++) { s[j] = __expf(s[j]); sum += s[j]; }
        sum += __shfl_xor_sync(~0u, sum, 1);
        sum += __shfl_xor_sync(~0u, sum, 2);
        float is = 1.0f / sum;
#pragma unroll
        for (int j = 0; j < 16; j++) Ks[m * 64 + q * 16 + j] = s[j] * is;
    }
    __syncthreads();
    if (tid < 64) {
        float a = 0.f;
        for (int i = 0; i < 64; i++) a += Ks[i * 64 + tid];
        cs[tid] = a;
    }
    __syncthreads();
    float sc = cs[0];
    for (int j = 1; j < 64; j++) sc = fmaxf(sc, cs[j]);
    float rs = 1.0f / sc;
    for (int e = tid; e < 4096; e += 256) {
        int i = e >> 6, j = e & 63;
        bufs[0][e] = Ks[j * 64 + i] * rs;
    }
    __syncthreads();
    int vi = 0;
#pragma unroll 1
    for (int it = 0; it < 6; ++it) {
        float* pv = bufs[vi];
        float* f1 = bufs[(vi + 1) & 3];
        float* f2 = bufs[(vi + 2) & 3];
        float* f3 = bufs[(vi + 3) & 3];
        mm64(f1, Ks, pv, tid, 1.0f);
        cIminus(f2, 7.0f, f1, tid);
        mm64(f3, f1, f2, tid, 1.0f);
        cIminus(f2, 15.0f, f3, tid);
        mm64(f3, f1, f2, tid, 1.0f);
        cIminus(f2, 13.0f, f3, tid);
        mm64(f3, pv, f2, tid, 0.25f);
        vi = (vi + 3) & 3;
    }
    __syncthreads();
    float* pv = bufs[vi];
    for (int e = tid * 4; e < 4096; e += 1024)
        *(float4*)(g_inv + lb + e) = *(const float4*)(pv + e);
}

// ======= kernel3 part: exp(Ql·K^T)·V over 8 tiles (no-max, scores tiny) ====
__global__ void __launch_bounds__(256) k3v_part()
{
    extern __shared__ float s[];
    float* Qls = s;             // [d][m] stride 68
    float* Kt  = s + 4352;      // [d][n] stride 68
    float* Ps  = s + 8704;      // [n][m] stride 68
    float* Vt  = s + 13056;     // [n][d] stride 64
    int bh = blockIdx.x, sp = blockIdx.y, tid = threadIdx.x;
    int tm = tid >> 4, tn = tid & 15;
    size_t base = (size_t)bh * NC * DC;

    for (int f = tid; f < 1024; f += 256) {
        int n = f >> 4, dg = (f & 15) * 4;
        float4 v = *(const float4*)(g_Ql + (size_t)bh * 4096 + n * 64 + dg);
        Qls[(dg+0)*68+n] = v.x; Qls[(dg+1)*68+n] = v.y;
        Qls[(dg+2)*68+n] = v.z; Qls[(dg+3)*68+n] = v.w;
    }
    float o[4][4], gsum[4];
#pragma unroll
    for (int i = 0; i < 4; i++) {
        gsum[i] = 0.f;
#pragma unroll
        for (int j = 0; j < 4; j++) o[i][j] = 0.f;
    }

    int ntile = NC / 64 / NSPL;   // 8
    for (int t = sp * ntile; t < (sp + 1) * ntile; t++) {
        __syncthreads();
        for (int f = tid; f < 1024; f += 256) {
            int n = f >> 4, dg = (f & 15) * 4;
            float4 kv = *(const float4*)(g_K + base + (size_t)t * 4096 + n * 64 + dg);
            Kt[(dg+0)*68+n] = kv.x; Kt[(dg+1)*68+n] = kv.y;
            Kt[(dg+2)*68+n] = kv.z; Kt[(dg+3)*68+n] = kv.w;
            *(float4*)(Vt + n * 64 + dg) =
                *(const float4*)(g_V + base + (size_t)t * 4096 + n * 64 + dg);
        }
        __syncthreads();

        float sc[4][4];
#pragma unroll
        for (int i = 0; i < 4; i++)
#pragma unroll
            for (int j = 0; j < 4; j++) sc[i][j] = 0.f;
#pragma unroll 8
        for (int d = 0; d < 64; d++) {
            float4 q = *(const float4*)(Qls + d * 68 + tm * 4);
            float4 k = *(const float4*)(Kt + d * 68 + tn * 4);
            float qa[4] = {q.x, q.y, q.z, q.w};
            float ka[4] = {k.x, k.y, k.z, k.w};
#pragma unroll
            for (int i = 0; i < 4; i++)
#pragma unroll
                for (int j = 0; j < 4; j++) sc[i][j] = fmaf(qa[i], ka[j], sc[i][j]);
        }
#pragma unroll
        for (int i = 0; i < 4; i++) {
#pragma unroll
            for (int j = 0; j < 4; j++) {
                float p = __expf(sc[i][j]);
                Ps[(tn * 4 + j) * 68 + tm * 4 + i] = p;
                gsum[i] += p;
            }
        }
        __syncthreads();
#pragma unroll 8
        for (int n = 0; n < 64; n++) {
            float4 p = *(const float4*)(Ps + n * 68 + tm * 4);
            float4 v = *(const float4*)(Vt + n * 64 + tn * 4);
            float pa[4] = {p.x, p.y, p.z, p.w};
            float va[4] = {v.x, v.y, v.z, v.w};
#pragma unroll
            for (int i = 0; i < 4; i++)
#pragma unroll
                for (int j = 0; j < 4; j++) o[i][j] = fmaf(pa[i], va[j], o[i][j]);
        }
    }
    // reduce gsum across the 16 threads of each tm group
#pragma unroll
    for (int i = 0; i < 4; i++) {
        gsum[i] += __shfl_xor_sync(~0u, gsum[i], 1);
        gsum[i] += __shfl_xor_sync(~0u, gsum[i], 2);
        gsum[i] += __shfl_xor_sync(~0u, gsum[i], 4);
        gsum[i] += __shfl_xor_sync(~0u, gsum[i], 8);
    }
    size_t pb = ((size_t)bh * NSPL + sp) * 4096;
#pragma unroll
    for (int i = 0; i < 4; i++) {
        float4 w = { o[i][0], o[i][1], o[i][2], o[i][3] };
        *(float4*)(g_pacc + pb + (tm * 4 + i) * 64 + tn * 4) = w;
    }
    if (tn == 0) {
        int mb = (bh * NSPL + sp) * 64 + tm * 4;
#pragma unroll
        for (int i = 0; i < 4; i++) g_psum[mb + i] = gsum[i];
    }
}

__global__ void __launch_bounds__(256) k3v_combine()
{
    __shared__ float inv_s[64];
    int bh = blockIdx.x, tid = threadIdx.x;
    if (tid < 64) {
        float tot = 0.f;
#pragma unroll
        for (int s2 = 0; s2 < NSPL; s2++) tot += g_psum[(bh * NSPL + s2) * 64 + tid];
        inv_s[tid] = 1.0f / tot;
    }
    __syncthreads();
    size_t pb = (size_t)bh * NSPL * 4096;
    for (int e = tid * 4; e < 4096; e += 1024) {
        int m = e >> 6;
        float4 o = make_float4(0.f, 0.f, 0.f, 0.f);
#pragma unroll
        for (int s2 = 0; s2 < NSPL; s2++) {
            float4 a = *(const float4*)(g_pacc + pb + s2*4096 + e);
            o.x += a.x; o.y += a.y; o.z += a.z; o.w += a.w;
        }
        float iv = inv_s[m];
        o.x *= iv; o.y *= iv; o.z *= iv; o.w *= iv;
        *(float4*)(g_k3V + (size_t)bh * 4096 + e) = o;
    }
}

// ===== kernel1: softmax -> x inv -> x k3V, 4 row-batches per block =========
__global__ void __launch_bounds__(256) k1_kernel()
{
    extern __shared__ float s[];
    float* Qt   = s;                  // [d][n] 68
    float* Kls  = s + 4352;           // [d][m] 68
    float* Ps   = s + 8704;           // [m][n] 68
    float* Ts   = s + 13056;          // [j][n] 68
    float* invs = s + 17408;          // [m][j] 64
    float* kvs  = s + 21504;          // [j][d] 64
    int bh = blockIdx.x;
    int b = bh / HC, h = bh - b * HC;
    int tid = threadIdx.x, tn = tid >> 4, tc = tid & 15;
    size_t lb = (size_t)bh * 4096;

    for (int f = tid; f < 1024; f += 256) {
        int r = f >> 4, dg = (f & 15) * 4;
        float4 kl = *(const float4*)(g_Kl + lb + r * 64 + dg);
        Kls[(dg+0)*68+r] = kl.x; Kls[(dg+1)*68+r] = kl.y;
        Kls[(dg+2)*68+r] = kl.z; Kls[(dg+3)*68+r] = kl.w;
        *(float4*)(invs + r * 64 + dg) = *(const float4*)(g_inv + lb + r * 64 + dg);
        *(float4*)(kvs + r * 64 + dg)  = *(const float4*)(g_k3V + lb + r * 64 + dg);
    }

    for (int bat = 0; bat < 4; bat++) {
        int n0 = blockIdx.y * 256 + bat * 64;
        size_t qbase = ((size_t)bh * NC + n0) * DC;
        __syncthreads();
        for (int f = tid; f < 1024; f += 256) {
            int r = f >> 4, dg = (f & 15) * 4;
            float4 q = *(const float4*)(g_Q + qbase + r * 64 + dg);
            Qt[(dg+0)*68+r] = q.x; Qt[(dg+1)*68+r] = q.y;
            Qt[(dg+2)*68+r] = q.z; Qt[(dg+3)*68+r] = q.w;
        }
        __syncthreads();

        float sc[4][4];
#pragma unroll
        for (int i = 0; i < 4; i++)
#pragma unroll
            for (int j = 0; j < 4; j++) sc[i][j] = 0.f;
#pragma unroll 8
        for (int d = 0; d < 64; d++) {
            float4 q = *(const float4*)(Qt + d * 68 + tn * 4);
            float4 k = *(const float4*)(Kls + d * 68 + tc * 4);
            float qa[4] = {q.x,q.y,q.z,q.w}, ka[4] = {k.x,k.y,k.z,k.w};
#pragma unroll
            for (int i = 0; i < 4; i++)
#pragma unroll
                for (int j = 0; j < 4; j++) sc[i][j] = fmaf(qa[i], ka[j], sc[i][j]);
        }
#pragma unroll
        for (int i = 0; i < 4; i++) {
            float p[4], ts = 0.f;
#pragma unroll
            for (int j = 0; j < 4; j++) { p[j] = __expf(sc[i][j]); ts += p[j]; }
            ts += __shfl_xor_sync(~0u, ts, 1);
            ts += __shfl_xor_sync(~0u, ts, 2);
            ts += __shfl_xor_sync(~0u, ts, 4);
            ts += __shfl_xor_sync(~0u, ts, 8);
            float is = 1.0f / ts;
#pragma unroll
            for (int j = 0; j < 4; j++)
                Ps[(tc * 4 + j) * 68 + tn * 4 + i] = p[j] * is;
        }
        __syncthreads();

        float tt[4][4];
#pragma unroll
        for (int i = 0; i < 4; i++)
#pragma unroll
            for (int j = 0; j < 4; j++) tt[i][j] = 0.f;
#pragma unroll 8
        for (int m = 0; m < 64; m++) {
            float4 p = *(const float4*)(Ps + m * 68 + tn * 4);
            float4 iv = *(const float4*)(invs + m * 64 + tc * 4);
            float pa[4] = {p.x,p.y,p.z,p.w}, ia[4] = {iv.x,iv.y,iv.z,iv.w};
#pragma unroll
            for (int i = 0; i < 4; i++)
#pragma unroll
                for (int j = 0; j < 4; j++) tt[i][j] = fmaf(pa[i], ia[j], tt[i][j]);
        }
#pragma unroll
        for (int i = 0; i < 4; i++)
#pragma unroll
            for (int j = 0; j < 4; j++)
                Ts[(tc * 4 + j) * 68 + tn * 4 + i] = tt[i][j];
        __syncthreads();

        float o[4][4];
#pragma unroll
        for (int i = 0; i < 4; i++)
#pragma unroll
            for (int j = 0; j < 4; j++) o[i][j] = 0.f;
#pragma unroll 8
        for (int jj = 0; jj < 64; jj++) {
            float4 t4 = *(const float4*)(Ts + jj * 68 + tn * 4);
            float4 kv = *(const float4*)(kvs + jj * 64 + tc * 4);
            float ta[4] = {t4.x,t4.y,t4.z,t4.w}, ka[4] = {kv.x,kv.y,kv.z,kv.w};
#pragma unroll
            for (int i = 0; i < 4; i++)
#pragma unroll
                for (int j = 0; j < 4; j++) o[i][j] = fmaf(ta[i], ka[j], o[i][j]);
        }
#pragma unroll
        for (int i = 0; i < 4; i++) {
            int n = n0 + tn * 4 + i;
            float4 w = { o[i][0], o[i][1], o[i][2], o[i][3] };
            *(float4*)(g_SV + ((size_t)b * NC + n) * CC + h * 64 + tc * 4) = w;
        }
    }
}

// ===================== launcher =====================
extern "C" void kernel_launch(void* const* d_in, const int* in_sizes, int n_in,
                              void* d_out, int out_size)
{
    (void)in_sizes; (void)n_in; (void)out_size;
    const float* x      = (const float*)d_in[0];
    const float* w_qkv  = (const float*)d_in[1];
    const float* w_proj = (const float*)d_in[2];
    const float* b_proj = (const float*)d_in[3];
    float* out = (float*)d_out;

    cudaFuncSetAttribute(mma_gemm<0>, cudaFuncAttributeMaxDynamicSharedMemorySize, 73728);
    cudaFuncSetAttribute(mma_gemm<1>, cudaFuncAttributeMaxDynamicSharedMemorySize, 73728);
    cudaFuncSetAttribute(inv_kernel, cudaFuncAttributeMaxDynamicSharedMemorySize, 5*4096*4);
    cudaFuncSetAttribute(k3v_part,   cudaFuncAttributeMaxDynamicSharedMemorySize, 68608);
    cudaFuncSetAttribute(k1_kernel,  cudaFuncAttributeMaxDynamicSharedMemorySize, 102400);

    mma_gemm<0><<<dim3(18, 256), 256, 73728>>>(x, w_qkv, nullptr, nullptr);
    landmarks_kernel<<<BHC * MC, 64>>>();
    inv_kernel<<<BHC, 256, 5*4096*4>>>();
    k3v_part<<<dim3(BHC, NSPL), 256, 68608>>>();
    k3v_combine<<<BHC, 256>>>();
    k1_kernel<<<dim3(BHC, 16), 256, 102400>>>();
    mma_gemm<1><<<dim3(6, 256), 256, 73728>>>(nullptr, w_proj, out, b_proj);
}